// round 13
// baseline (speedup 1.0000x reference)
#include <cuda_runtime.h>
#include <cuda_fp16.h>
#include <math.h>
#include <stdint.h>

#define Bb 2
#define Tt 2048
#define Cc 1024
#define Hh 16
#define Dd 64

__device__ __half g_xn [Bb*Tt*Cc];
__device__ __half g_qv [Bb*Tt*2*Cc];
__device__ __half g_att[Bb*Tt*Cc];
__device__ float  g_x1 [Bb*Tt*Cc];
__device__ __half g_h  [Bb*Tt*4*Cc];
__device__ __half g_wqv[2*Cc*Cc];
__device__ __half g_wo [Cc*Cc];
__device__ __half g_w1 [4*Cc*Cc];
__device__ __half g_w2 [Cc*4*Cc];
__device__ float  g_qvb[2*Cc];
__device__ __half g_eh [Hh*Tt*Dd];

#define CPA16(dst, src) \
    asm volatile("cp.async.cg.shared.global [%0], [%1], 16;" :: "r"(dst), "l"(src) : "memory")

// ======================== fused prep ========================
__global__ void prep_all(const float* __restrict__ qkv_w, const float* __restrict__ out_w,
                         const float* __restrict__ mlp_w1, const float* __restrict__ mlp_w2,
                         const float* __restrict__ qkv_b, const float* __restrict__ enc,
                         __half* __restrict__ wqv, __half* __restrict__ wo,
                         __half* __restrict__ w1,  __half* __restrict__ w2,
                         float* __restrict__ qvb,  __half* __restrict__ eh){
    const int id = blockIdx.x;
    const int tx = threadIdx.x, ty = threadIdx.y;
    if (id >= 12288){
        int i = (id - 12288) * 256 + ty*32 + tx;
        qvb[i] = (i < Cc) ? qkv_b[i] : qkv_b[i + Cc];
        return;
    }
    if (id >= 11264){
        int i = ((id - 11264) * 256 + ty*32 + tx) * 8;
        float4 a = *(const float4*)(enc + i);
        float4 c = *(const float4*)(enc + i + 4);
        __half2 h0 = __floats2half2_rn(a.x, a.y);
        __half2 h1 = __floats2half2_rn(a.z, a.w);
        __half2 h2 = __floats2half2_rn(c.x, c.y);
        __half2 h3 = __floats2half2_rn(c.z, c.w);
        *(uint4*)(eh + i) = make_uint4(*(uint32_t*)&h0, *(uint32_t*)&h1,
                                       *(uint32_t*)&h2, *(uint32_t*)&h3);
        return;
    }
    const float* W; __half* Wt; int ldw, K, ntn, base;
    if      (id < 1024){ W = qkv_w;          Wt = wqv;         ldw = 3*Cc; K = Cc;   ntn = 32;  base = id; }
    else if (id < 2048){ W = qkv_w + 2*Cc;   Wt = wqv + Cc*Cc; ldw = 3*Cc; K = Cc;   ntn = 32;  base = id - 1024; }
    else if (id < 3072){ W = out_w;          Wt = wo;          ldw = Cc;   K = Cc;   ntn = 32;  base = id - 2048; }
    else if (id < 7168){ W = mlp_w1;         Wt = w1;          ldw = 4*Cc; K = Cc;   ntn = 128; base = id - 3072; }
    else               { W = mlp_w2;         Wt = w2;          ldw = Cc;   K = 4*Cc; ntn = 32;  base = id - 7168; }
    const int n0 = (base % ntn) * 32, k0 = (base / ntn) * 32;
    __shared__ float t[32][33];
    #pragma unroll
    for (int i = 0; i < 4; i++)
        t[ty + i*8][tx] = W[(size_t)(k0 + ty + i*8) * ldw + n0 + tx];
    __syncthreads();
    #pragma unroll
    for (int i = 0; i < 4; i++)
        Wt[(size_t)(n0 + ty + i*8) * K + k0 + tx] = __float2half_rn(t[tx][ty + i*8]);
}

// ======================== block reduce / LayerNorm ========================
__device__ __forceinline__ float block_sum(float v, volatile float* red){
    #pragma unroll
    for (int o = 16; o; o >>= 1) v += __shfl_xor_sync(0xffffffffu, v, o);
    int lane = threadIdx.x & 31, w = threadIdx.x >> 5;
    if (lane == 0) red[w] = v;
    __syncthreads();
    if (w == 0){
        v = (lane < 8) ? red[lane] : 0.f;
        #pragma unroll
        for (int o = 4; o; o >>= 1) v += __shfl_xor_sync(0xffffffffu, v, o);
    }
    return v;
}

__global__ void ln_kernel(const float* __restrict__ x, const float* __restrict__ g,
                          const float* __restrict__ b, __half* __restrict__ out){
    __shared__ float red[8];
    __shared__ float s_mu, s_rs;
    int row = blockIdx.x, tid = threadIdx.x;
    const float4 v = ((const float4*)(x + (size_t)row * Cc))[tid];
    float s = v.x + v.y + v.z + v.w;
    s = block_sum(s, red);
    if (tid == 0) s_mu = s * (1.0f / Cc);
    __syncthreads();
    float mu = s_mu;
    float dx = v.x - mu, dy = v.y - mu, dz = v.z - mu, dw = v.w - mu;
    float sq = dx*dx + dy*dy + dz*dz + dw*dw;
    sq = block_sum(sq, red);
    if (tid == 0) s_rs = rsqrtf(sq * (1.0f / Cc) + 1e-5f);
    __syncthreads();
    float rs = s_rs;
    float4 gg = ((const float4*)g)[tid], bb = ((const float4*)b)[tid];
    __half2 h0 = __floats2half2_rn(dx * rs * gg.x + bb.x, dy * rs * gg.y + bb.y);
    __half2 h1 = __floats2half2_rn(dz * rs * gg.z + bb.z, dw * rs * gg.w + bb.w);
    __half2* op = (__half2*)(out + (size_t)row * Cc);
    op[tid*2]     = h0;
    op[tid*2 + 1] = h1;
}

// ======================== fp16 GEMM (BK=32, 4-stage cp.async) ========================
#define HSTR 40
#define NSTG 4
#define STG_H (128*HSTR)
#define GH_SMEM (NSTG * STG_H * 2 * 2)

template<bool OUT_HALF>
__global__ __launch_bounds__(256) void gemm_h(
        const __half* __restrict__ A,
        const __half* __restrict__ Bt,
        const float* __restrict__ bias,
        const float* __restrict__ resid,
        void* __restrict__ outv,
        int N, int K, int do_gelu){
    extern __shared__ __half smh[];
    __half* As = smh;
    __half* Bs = smh + NSTG * STG_H;
    const int tid = threadIdx.x;
    const int lane = tid & 31, w = tid >> 5;
    const int warpM = (w & 1) * 64, warpN = (w >> 1) * 32;
    const int row0 = blockIdx.y * 128, col0 = blockIdx.x * 128;

    const int sr = tid >> 1;
    const int kh = (tid & 1) * 16;
    const __half* Ap = A + (size_t)(row0 + sr) * K + kh;
    const __half* Bp = Bt + (size_t)(col0 + sr) * K + kh;
    const uint32_t adst = (uint32_t)__cvta_generic_to_shared(&As[sr*HSTR + kh]);
    const uint32_t bdst = (uint32_t)__cvta_generic_to_shared(&Bs[sr*HSTR + kh]);

    auto load_chunk = [&](int c, int s){
        uint32_t ao = adst + s * STG_H * 2;
        uint32_t bo = bdst + s * STG_H * 2;
        const __half* ag = Ap + c * 32;
        const __half* bg = Bp + c * 32;
        CPA16(ao, ag); CPA16(ao + 16, ag + 8);
        CPA16(bo, bg); CPA16(bo + 16, bg + 8);
        asm volatile("cp.async.commit_group;" ::: "memory");
    };

    float acc[4][4][4] = {};

    const int a_row = lane & 15;
    const int a_col = (lane >> 4) * 8;
    const int b_row = (lane & 7) + ((lane >> 4) << 3);
    const int b_col = ((lane >> 3) & 1) * 8;

    auto compute = [&](int s){
        const __half* Ab = As + s * STG_H;
        const __half* Bb2 = Bs + s * STG_H;
        #pragma unroll
        for (int kk = 0; kk < 2; kk++){
            uint32_t afr[4][4];
            #pragma unroll
            for (int mt = 0; mt < 4; mt++){
                uint32_t addr = (uint32_t)__cvta_generic_to_shared(
                    &Ab[(warpM + mt*16 + a_row) * HSTR + kk*16 + a_col]);
                asm volatile("ldmatrix.sync.aligned.m8n8.x4.shared.b16 {%0,%1,%2,%3}, [%4];"
                    : "=r"(afr[mt][0]), "=r"(afr[mt][1]), "=r"(afr[mt][2]), "=r"(afr[mt][3])
                    : "r"(addr));
            }
            uint32_t bfr[2][4];
            #pragma unroll
            for (int ng = 0; ng < 2; ng++){
                uint32_t addr = (uint32_t)__cvta_generic_to_shared(
                    &Bb2[(warpN + ng*16 + b_row) * HSTR + kk*16 + b_col]);
                asm volatile("ldmatrix.sync.aligned.m8n8.x4.shared.b16 {%0,%1,%2,%3}, [%4];"
                    : "=r"(bfr[ng][0]), "=r"(bfr[ng][1]), "=r"(bfr[ng][2]), "=r"(bfr[ng][3])
                    : "r"(addr));
            }
            #pragma unroll
            for (int mt = 0; mt < 4; mt++)
                #pragma unroll
                for (int nt = 0; nt < 4; nt++){
                    uint32_t b0 = bfr[nt >> 1][(nt & 1) * 2];
                    uint32_t b1 = bfr[nt >> 1][(nt & 1) * 2 + 1];
                    asm volatile(
                        "mma.sync.aligned.m16n8k16.row.col.f32.f16.f16.f32 "
                        "{%0,%1,%2,%3},{%4,%5,%6,%7},{%8,%9},{%0,%1,%2,%3};"
                        : "+f"(acc[mt][nt][0]), "+f"(acc[mt][nt][1]),
                          "+f"(acc[mt][nt][2]), "+f"(acc[mt][nt][3])
                        : "r"(afr[mt][0]), "r"(afr[mt][1]), "r"(afr[mt][2]), "r"(afr[mt][3]),
                          "r"(b0), "r"(b1));
                }
        }
    };

    const int ntiles = K / 32;
    load_chunk(0, 0); load_chunk(1, 1); load_chunk(2, 2);
    for (int t = 0; t < ntiles; t++){
        asm volatile("cp.async.wait_group 2;" ::: "memory");
        __syncthreads();
        if (t + 3 < ntiles) load_chunk(t + 3, (t + 3) & 3);
        compute(t & 3);
    }

    #pragma unroll
    for (int mt = 0; mt < 4; mt++){
        #pragma unroll
        for (int nt = 0; nt < 4; nt++){
            int rr = row0 + warpM + mt*16 + (lane >> 2);
            int cc = col0 + warpN + nt*8 + (lane & 3) * 2;
            #pragma unroll
            for (int half = 0; half < 2; half++){
                int r = rr + half * 8;
                float v0 = acc[mt][nt][half*2]     + bias[cc];
                float v1 = acc[mt][nt][half*2 + 1] + bias[cc + 1];
                if (resid){
                    const float2 rv = *(const float2*)&resid[(size_t)r * N + cc];
                    v0 += rv.x; v1 += rv.y;
                }
                if (do_gelu){
                    v0 = 0.5f * v0 * (1.f + erff(v0 * 0.70710678118f));
                    v1 = 0.5f * v1 * (1.f + erff(v1 * 0.70710678118f));
                }
                if (OUT_HALF){
                    *(__half2*)&((__half*)outv)[(size_t)r * N + cc] = __floats2half2_rn(v0, v1);
                } else {
                    *(float2*)&((float*)outv)[(size_t)r * N + cc] = make_float2(v0, v1);
                }
            }
        }
    }
}

// ======================== Attention: 32-key sub-tiles, log2 LIF ========================
#define HQ 72
#define QVLD (2*Cc)
#define ATTN_SMEM ((128 + 128 + 128) * HQ * 2)

__device__ __forceinline__ float rcp_a(float x){ float r; asm("rcp.approx.f32 %0,%1;" : "=f"(r) : "f"(x)); return r; }
__device__ __forceinline__ float lg2_a(float x){ float r; asm("lg2.approx.f32 %0,%1;" : "=f"(r) : "f"(x)); return r; }
__device__ __forceinline__ float ex2_a(float x){ float r; asm("ex2.approx.f32 %0,%1;" : "=f"(r) : "f"(x)); return r; }

__device__ __forceinline__ float lif_s2(float I){
    float u  = rcp_a(I);
    float wv = 1.0f - u;
    float lg = lg2_a(wv);
    float dd = fmaf(lg, -0.0138629436112f, 0.002f);
    float s2 = rcp_a(dd) * 0.180336879f;
    return (I > 1.0000001f) ? s2 : 0.0f;
}

__global__ __launch_bounds__(256) void attn_tc(
        const __half* __restrict__ Q, const __half* __restrict__ V,
        const __half* __restrict__ EH, const float* __restrict__ gain,
        const float* __restrict__ bias, __half* __restrict__ out){
    extern __shared__ __half smh[];
    __half* PsH = smh;
    __half* EsH = smh + 128*HQ;
    __half* VsH = smh + (128 + 128)*HQ;

    const int tid = threadIdx.x;
    const int lane = tid & 31, w = tid >> 5;
    const int bh = blockIdx.y, b = bh >> 4, h = bh & 15;
    const int t0 = (gridDim.x - 1 - blockIdx.x) << 7;
    const int rowbase = w << 4;

    const int a_row = lane & 15;
    const int a_col = (lane >> 4) * 8;
    const int b_row = (lane & 7) + ((lane >> 4) << 3);
    const int b_col = ((lane >> 3) & 1) * 8;
    const int v_row = (lane & 7) + ((lane >> 3) & 1) * 8;
    const int v_col = (lane >> 4) * 8;

    {
        const int qr = tid >> 1, qc = (tid & 1) * 32;
        const __half* qp = Q + ((size_t)(b*Tt + t0 + qr)) * QVLD + h*Dd + qc;
        #pragma unroll
        for (int j = 0; j < 4; j++)
            *(uint4*)&PsH[qr*HQ + qc + j*8] = *(const uint4*)(qp + j*8);
    }
    __syncthreads();

    uint32_t qa[4][4];
    #pragma unroll
    for (int kk = 0; kk < 4; kk++){
        uint32_t addr = (uint32_t)__cvta_generic_to_shared(
            &PsH[(rowbase + a_row) * HQ + kk*16 + a_col]);
        asm volatile("ldmatrix.sync.aligned.m8n8.x4.shared.b16 {%0,%1,%2,%3}, [%4];"
            : "=r"(qa[kk][0]), "=r"(qa[kk][1]), "=r"(qa[kk][2]), "=r"(qa[kk][3])
            : "r"(addr));
    }

    const int r = lane >> 2;
    const int cq = (lane & 3) << 1;
    const int tA = t0 + rowbase + r;
    const int tB = tA + 8;
    const float gA = gain[h*Tt + tA], bA = bias[h*Tt + tA];
    const float gB = gain[h*Tt + tB], bB = bias[h*Tt + tB];
    const int twmax = t0 + rowbase + 15;
    const int wmin  = t0 + rowbase;

    float oacc[8][4] = {};
    float psumA = 0.f, psumB = 0.f;
    float mA = 0.f, mB = 0.f;

    const int s_lr = tid >> 2;
    const int s_ck = (tid & 3) * 16;
    auto stage_tile = [&](int s0, int sbuf){
        const __half* eg = EH + ((size_t)(h*Tt + s0 + s_lr)) * Dd + s_ck;
        uint32_t ed = (uint32_t)__cvta_generic_to_shared(&EsH[sbuf*64*HQ + s_lr*HQ + s_ck]);
        CPA16(ed, eg); CPA16(ed + 16, eg + 8);
        const __half* vg = V + ((size_t)(b*Tt + s0 + s_lr)) * QVLD + h*Dd + s_ck;
        uint32_t vd = (uint32_t)__cvta_generic_to_shared(&VsH[sbuf*64*HQ + s_lr*HQ + s_ck]);
        CPA16(vd, vg); CPA16(vd + 16, vg + 8);
        asm volatile("cp.async.commit_group;" ::: "memory");
    };

    const int nIt = (t0 >> 6) + 2;
    stage_tile(0, 0);
    int buf = 0;

    for (int it = 0; it < nIt; it++){
        const int s0 = it << 6;
        asm volatile("cp.async.wait_group 0;" ::: "memory");
        __syncthreads();
        if (it + 1 < nIt) stage_tile(s0 + 64, buf ^ 1);

        if (s0 <= twmax){
            const __half* Eb = EsH + buf*64*HQ;
            const __half* Vb = VsH + buf*64*HQ;

            // -------- two 32-key sub-tiles, processed end-to-end --------
            #pragma unroll
            for (int sub = 0; sub < 2; sub++){
                const int sbase = s0 + sub*32;
                if (sbase > twmax) continue;

                // ---- MMA1-half: S[16x32] = Q . E^T
                float sacc[4][4] = {};
                #pragma unroll
                for (int kk = 0; kk < 4; kk++){
                    uint32_t bfr[2][4];
                    #pragma unroll
                    for (int ng = 0; ng < 2; ng++){
                        uint32_t addr = (uint32_t)__cvta_generic_to_shared(
                            &Eb[(sub*32 + ng*16 + b_row) * HQ + kk*16 + b_col]);
                        asm volatile("ldmatrix.sync.aligned.m8n8.x4.shared.b16 {%0,%1,%2,%3}, [%4];"
                            : "=r"(bfr[ng][0]), "=r"(bfr[ng][1]), "=r"(bfr[ng][2]), "=r"(bfr[ng][3])
                            : "r"(addr));
                    }
                    #pragma unroll
                    for (int nt = 0; nt < 4; nt++){
                        uint32_t b0 = bfr[nt >> 1][(nt & 1) * 2];
                        uint32_t b1 = bfr[nt >> 1][(nt & 1) * 2 + 1];
                        asm volatile(
                            "mma.sync.aligned.m16n8k16.row.col.f32.f16.f16.f32 "
                            "{%0,%1,%2,%3},{%4,%5,%6,%7},{%8,%9},{%0,%1,%2,%3};"
                            : "+f"(sacc[nt][0]), "+f"(sacc[nt][1]),
                              "+f"(sacc[nt][2]), "+f"(sacc[nt][3])
                            : "r"(qa[kk][0]), "r"(qa[kk][1]), "r"(qa[kk][2]), "r"(qa[kk][3]),
                              "r"(b0), "r"(b1));
                    }
                }

                // ---- LIF (log2) + causal
                float tmaxA = 0.f, tmaxB = 0.f;
                if (sbase + 31 <= wmin){
                    #pragma unroll
                    for (int nt = 0; nt < 4; nt++){
                        float v00 = lif_s2(fmaf(gA, sacc[nt][0], bA));
                        float v01 = lif_s2(fmaf(gA, sacc[nt][1], bA));
                        float v10 = lif_s2(fmaf(gB, sacc[nt][2], bB));
                        float v11 = lif_s2(fmaf(gB, sacc[nt][3], bB));
                        sacc[nt][0] = v00; sacc[nt][1] = v01; sacc[nt][2] = v10; sacc[nt][3] = v11;
                        tmaxA = fmaxf(tmaxA, fmaxf(v00, v01));
                        tmaxB = fmaxf(tmaxB, fmaxf(v10, v11));
                    }
                } else {
                    #pragma unroll
                    for (int nt = 0; nt < 4; nt++){
                        int sb = sbase + nt*8 + cq;
                        float v00 = (sb     <= tA) ? lif_s2(fmaf(gA, sacc[nt][0], bA)) : -1e30f;
                        float v01 = (sb + 1 <= tA) ? lif_s2(fmaf(gA, sacc[nt][1], bA)) : -1e30f;
                        float v10 = (sb     <= tB) ? lif_s2(fmaf(gB, sacc[nt][2], bB)) : -1e30f;
                        float v11 = (sb + 1 <= tB) ? lif_s2(fmaf(gB, sacc[nt][3], bB)) : -1e30f;
                        sacc[nt][0] = v00; sacc[nt][1] = v01; sacc[nt][2] = v10; sacc[nt][3] = v11;
                        tmaxA = fmaxf(tmaxA, fmaxf(v00, v01));
                        tmaxB = fmaxf(tmaxB, fmaxf(v10, v11));
                    }
                }
                tmaxA = fmaxf(tmaxA, __shfl_xor_sync(0xffffffffu, tmaxA, 1));
                tmaxA = fmaxf(tmaxA, __shfl_xor_sync(0xffffffffu, tmaxA, 2));
                tmaxB = fmaxf(tmaxB, __shfl_xor_sync(0xffffffffu, tmaxB, 1));
                tmaxB = fmaxf(tmaxB, __shfl_xor_sync(0xffffffffu, tmaxB, 2));

                if (__any_sync(0xffffffffu, (tmaxA > mA) || (tmaxB > mB))){
                    float mAn = fmaxf(mA, tmaxA), mBn = fmaxf(mB, tmaxB);
                    float scA = ex2_a(mA - mAn), scB = ex2_a(mB - mBn);
                    mA = mAn; mB = mBn;
                    psumA *= scA; psumB *= scB;
                    #pragma unroll
                    for (int nt = 0; nt < 8; nt++){
                        oacc[nt][0] *= scA; oacc[nt][1] *= scA;
                        oacc[nt][2] *= scB; oacc[nt][3] *= scB;
                    }
                }

                // ---- ex2 -> P fragments (2 k16-steps)
                uint32_t pa[2][4];
                #pragma unroll
                for (int nt = 0; nt < 4; nt++){
                    float p00 = ex2_a(sacc[nt][0] - mA);
                    float p01 = ex2_a(sacc[nt][1] - mA);
                    float p10 = ex2_a(sacc[nt][2] - mB);
                    float p11 = ex2_a(sacc[nt][3] - mB);
                    psumA += p00 + p01;
                    psumB += p10 + p11;
                    __half2 hA = __floats2half2_rn(p00, p01);
                    __half2 hB = __floats2half2_rn(p10, p11);
                    pa[nt >> 1][(nt & 1) * 2    ] = *(uint32_t*)&hA;
                    pa[nt >> 1][(nt & 1) * 2 + 1] = *(uint32_t*)&hB;
                }

                // ---- MMA2-half: O += P . V[sbase:sbase+32]
                #pragma unroll
                for (int kk2 = 0; kk2 < 2; kk2++){
                    uint32_t bfr[4][4];
                    #pragma unroll
                    for (int ng = 0; ng < 4; ng++){
                        uint32_t addr = (uint32_t)__cvta_generic_to_shared(
                            &Vb[(sub*32 + kk2*16 + v_row) * HQ + ng*16 + v_col]);
                        asm volatile("ldmatrix.sync.aligned.m8n8.x4.trans.shared.b16 {%0,%1,%2,%3}, [%4];"
                            : "=r"(bfr[ng][0]), "=r"(bfr[ng][1]), "=r"(bfr[ng][2]), "=r"(bfr[ng][3])
                            : "r"(addr));
                    }
                    #pragma unroll
                    for (int nt = 0; nt < 8; nt++){
                        uint32_t b0 = bfr[nt >> 1][(nt & 1) * 2];
                        uint32_t b1 = bfr[nt >> 1][(nt & 1) * 2 + 1];
                        asm volatile(
                            "mma.sync.aligned.m16n8k16.row.col.f32.f16.f16.f32 "
                            "{%0,%1,%2,%3},{%4,%5,%6,%7},{%8,%9},{%0,%1,%2,%3};"
                            : "+f"(oacc[nt][0]), "+f"(oacc[nt][1]),
                              "+f"(oacc[nt][2]), "+f"(oacc[nt][3])
                            : "r"(pa[kk2][0]), "r"(pa[kk2][1]), "r"(pa[kk2][2]), "r"(pa[kk2][3]),
                              "r"(b0), "r"(b1));
                    }
                }
            }
        }
        buf ^= 1;
    }

    psumA += __shfl_xor_sync(0xffffffffu, psumA, 1);
    psumA += __shfl_xor_sync(0xffffffffu, psumA, 2);
    psumB += __shfl_xor_sync(0xffffffffu, psumB, 1);
    psumB += __shfl_xor_sync(0xffffffffu, psumB, 2);
    float invA = 1.0f / psumA;
    float invB = 1.0f / psumB;

    __half* opA = out + ((size_t)(b*Tt + tA)) * Cc + h*Dd;
    __half* opB = out + ((size_t)(b*Tt + tB)) * Cc + h*Dd;
    #pragma unroll
    for (int nt = 0; nt < 8; nt++){
        int d = nt*8 + cq;
        *(__half2*)&opA[d] = __floats2half2_rn(oacc[nt][0]*invA, oacc[nt][1]*invA);
        *(__half2*)&opB[d] = __floats2half2_rn(oacc[nt][2]*invB, oacc[nt][3]*invB);
    }
}

// ======================== launch ========================
extern "C" void kernel_launch(void* const* d_in, const int* in_sizes, int n_in,
                              void* d_out, int out_size){
    const float* x      = (const float*)d_in[0];
    const float* ln1_g  = (const float*)d_in[1];
    const float* ln1_b  = (const float*)d_in[2];
    const float* qkv_w  = (const float*)d_in[3];
    const float* qkv_b  = (const float*)d_in[4];
    const float* out_w  = (const float*)d_in[5];
    const float* out_b  = (const float*)d_in[6];
    const float* ln2_g  = (const float*)d_in[7];
    const float* ln2_b  = (const float*)d_in[8];
    const float* mlp_w1 = (const float*)d_in[9];
    const float* mlp_b1 = (const float*)d_in[10];
    const float* mlp_w2 = (const float*)d_in[11];
    const float* mlp_b2 = (const float*)d_in[12];
    const float* enc    = (const float*)d_in[13];
    const float* gain   = (const float*)d_in[14];
    const float* battn  = (const float*)d_in[15];
    float* outp = (float*)d_out;

    __half *xn, *qv, *att, *hbuf, *wqv, *wo, *w1, *w2, *eh;
    float *x1, *qvb;
    cudaGetSymbolAddress((void**)&xn,   g_xn);
    cudaGetSymbolAddress((void**)&qv,   g_qv);
    cudaGetSymbolAddress((void**)&att,  g_att);
    cudaGetSymbolAddress((void**)&x1,   g_x1);
    cudaGetSymbolAddress((void**)&hbuf, g_h);
    cudaGetSymbolAddress((void**)&wqv,  g_wqv);
    cudaGetSymbolAddress((void**)&wo,   g_wo);
    cudaGetSymbolAddress((void**)&w1,   g_w1);
    cudaGetSymbolAddress((void**)&w2,   g_w2);
    cudaGetSymbolAddress((void**)&qvb,  g_qvb);
    cudaGetSymbolAddress((void**)&eh,   g_eh);

    cudaFuncSetAttribute(attn_tc,       cudaFuncAttributeMaxDynamicSharedMemorySize, ATTN_SMEM);
    cudaFuncSetAttribute(gemm_h<true>,  cudaFuncAttributeMaxDynamicSharedMemorySize, GH_SMEM);
    cudaFuncSetAttribute(gemm_h<false>, cudaFuncAttributeMaxDynamicSharedMemorySize, GH_SMEM);

    const int M = Bb * Tt;

    prep_all<<<12296, dim3(32,8)>>>(qkv_w, out_w, mlp_w1, mlp_w2, qkv_b, enc,
                                    wqv, wo, w1, w2, qvb, eh);

    ln_kernel<<<M, 256>>>(x, ln1_g, ln1_b, xn);
    gemm_h<true ><<<dim3(2*Cc/128, M/128), 256, GH_SMEM>>>(xn, wqv, qvb, nullptr, qv, 2*Cc, Cc, 0);
    attn_tc<<<dim3(Tt/128, Bb*Hh), 256, ATTN_SMEM>>>(qv, qv + Cc, eh, gain, battn, att);
    gemm_h<false><<<dim3(Cc/128, M/128), 256, GH_SMEM>>>(att, wo, out_b, x, x1, Cc, Cc, 0);
    ln_kernel<<<M, 256>>>(x1, ln2_g, ln2_b, xn);
    gemm_h<true ><<<dim3(4*Cc/128, M/128), 256, GH_SMEM>>>(xn, w1, mlp_b1, nullptr, hbuf, 4*Cc, Cc, 1);
    gemm_h<false><<<dim3(Cc/128, M/128), 256, GH_SMEM>>>(hbuf, w2, mlp_b2, x1, outp, Cc, 4*Cc, 0);
}

// round 14
// speedup vs baseline: 1.0346x; 1.0346x over previous
#include <cuda_runtime.h>
#include <cuda_fp16.h>
#include <math.h>
#include <stdint.h>

#define Bb 2
#define Tt 2048
#define Cc 1024
#define Hh 16
#define Dd 64

__device__ __half g_xn [Bb*Tt*Cc];
__device__ __half g_qv [Bb*Tt*2*Cc];
__device__ __half g_att[Bb*Tt*Cc];
__device__ float  g_x1 [Bb*Tt*Cc];
__device__ __half g_h  [Bb*Tt*4*Cc];
__device__ __half g_wqv[2*Cc*Cc];
__device__ __half g_wo [Cc*Cc];
__device__ __half g_w1 [4*Cc*Cc];
__device__ __half g_w2 [Cc*4*Cc];
__device__ float  g_qvb[2*Cc];
__device__ __half g_eh [Hh*Tt*Dd];

#define CPA16(dst, src) \
    asm volatile("cp.async.cg.shared.global [%0], [%1], 16;" :: "r"(dst), "l"(src) : "memory")

// ======================== fused prep ========================
__global__ void prep_all(const float* __restrict__ qkv_w, const float* __restrict__ out_w,
                         const float* __restrict__ mlp_w1, const float* __restrict__ mlp_w2,
                         const float* __restrict__ qkv_b, const float* __restrict__ enc,
                         __half* __restrict__ wqv, __half* __restrict__ wo,
                         __half* __restrict__ w1,  __half* __restrict__ w2,
                         float* __restrict__ qvb,  __half* __restrict__ eh){
    const int id = blockIdx.x;
    const int tx = threadIdx.x, ty = threadIdx.y;
    if (id >= 12288){
        int i = (id - 12288) * 256 + ty*32 + tx;
        qvb[i] = (i < Cc) ? qkv_b[i] : qkv_b[i + Cc];
        return;
    }
    if (id >= 11264){
        int i = ((id - 11264) * 256 + ty*32 + tx) * 8;
        float4 a = *(const float4*)(enc + i);
        float4 c = *(const float4*)(enc + i + 4);
        __half2 h0 = __floats2half2_rn(a.x, a.y);
        __half2 h1 = __floats2half2_rn(a.z, a.w);
        __half2 h2 = __floats2half2_rn(c.x, c.y);
        __half2 h3 = __floats2half2_rn(c.z, c.w);
        *(uint4*)(eh + i) = make_uint4(*(uint32_t*)&h0, *(uint32_t*)&h1,
                                       *(uint32_t*)&h2, *(uint32_t*)&h3);
        return;
    }
    const float* W; __half* Wt; int ldw, K, ntn, base;
    if      (id < 1024){ W = qkv_w;          Wt = wqv;         ldw = 3*Cc; K = Cc;   ntn = 32;  base = id; }
    else if (id < 2048){ W = qkv_w + 2*Cc;   Wt = wqv + Cc*Cc; ldw = 3*Cc; K = Cc;   ntn = 32;  base = id - 1024; }
    else if (id < 3072){ W = out_w;          Wt = wo;          ldw = Cc;   K = Cc;   ntn = 32;  base = id - 2048; }
    else if (id < 7168){ W = mlp_w1;         Wt = w1;          ldw = 4*Cc; K = Cc;   ntn = 128; base = id - 3072; }
    else               { W = mlp_w2;         Wt = w2;          ldw = Cc;   K = 4*Cc; ntn = 32;  base = id - 7168; }
    const int n0 = (base % ntn) * 32, k0 = (base / ntn) * 32;
    __shared__ float t[32][33];
    #pragma unroll
    for (int i = 0; i < 4; i++)
        t[ty + i*8][tx] = W[(size_t)(k0 + ty + i*8) * ldw + n0 + tx];
    __syncthreads();
    #pragma unroll
    for (int i = 0; i < 4; i++)
        Wt[(size_t)(n0 + ty + i*8) * K + k0 + tx] = __float2half_rn(t[tx][ty + i*8]);
}

// ======================== block reduce / LayerNorm ========================
__device__ __forceinline__ float block_sum(float v, volatile float* red){
    #pragma unroll
    for (int o = 16; o; o >>= 1) v += __shfl_xor_sync(0xffffffffu, v, o);
    int lane = threadIdx.x & 31, w = threadIdx.x >> 5;
    if (lane == 0) red[w] = v;
    __syncthreads();
    if (w == 0){
        v = (lane < 8) ? red[lane] : 0.f;
        #pragma unroll
        for (int o = 4; o; o >>= 1) v += __shfl_xor_sync(0xffffffffu, v, o);
    }
    return v;
}

__global__ void ln_kernel(const float* __restrict__ x, const float* __restrict__ g,
                          const float* __restrict__ b, __half* __restrict__ out){
    __shared__ float red[8];
    __shared__ float s_mu, s_rs;
    int row = blockIdx.x, tid = threadIdx.x;
    const float4 v = ((const float4*)(x + (size_t)row * Cc))[tid];
    float s = v.x + v.y + v.z + v.w;
    s = block_sum(s, red);
    if (tid == 0) s_mu = s * (1.0f / Cc);
    __syncthreads();
    float mu = s_mu;
    float dx = v.x - mu, dy = v.y - mu, dz = v.z - mu, dw = v.w - mu;
    float sq = dx*dx + dy*dy + dz*dz + dw*dw;
    sq = block_sum(sq, red);
    if (tid == 0) s_rs = rsqrtf(sq * (1.0f / Cc) + 1e-5f);
    __syncthreads();
    float rs = s_rs;
    float4 gg = ((const float4*)g)[tid], bb = ((const float4*)b)[tid];
    __half2 h0 = __floats2half2_rn(dx * rs * gg.x + bb.x, dy * rs * gg.y + bb.y);
    __half2 h1 = __floats2half2_rn(dz * rs * gg.z + bb.z, dw * rs * gg.w + bb.w);
    __half2* op = (__half2*)(out + (size_t)row * Cc);
    op[tid*2]     = h0;
    op[tid*2 + 1] = h1;
}

// ======================== fp16 GEMM (BK=32, 5-stage cp.async) ========================
#define HSTR 40
#define NSTG 5
#define STG_H (128*HSTR)
#define GH_SMEM (NSTG * STG_H * 2 * 2)   // 102400 bytes

template<bool OUT_HALF>
__global__ __launch_bounds__(256) void gemm_h(
        const __half* __restrict__ A,
        const __half* __restrict__ Bt,
        const float* __restrict__ bias,
        const float* __restrict__ resid,
        void* __restrict__ outv,
        int N, int K, int do_gelu){
    extern __shared__ __half smh[];
    __half* As = smh;
    __half* Bs = smh + NSTG * STG_H;
    const int tid = threadIdx.x;
    const int lane = tid & 31, w = tid >> 5;
    const int warpM = (w & 1) * 64, warpN = (w >> 1) * 32;
    const int row0 = blockIdx.y * 128, col0 = blockIdx.x * 128;

    const int sr = tid >> 1;
    const int kh = (tid & 1) * 16;
    const __half* Ap = A + (size_t)(row0 + sr) * K + kh;
    const __half* Bp = Bt + (size_t)(col0 + sr) * K + kh;
    const uint32_t adst = (uint32_t)__cvta_generic_to_shared(&As[sr*HSTR + kh]);
    const uint32_t bdst = (uint32_t)__cvta_generic_to_shared(&Bs[sr*HSTR + kh]);

    auto load_chunk = [&](int c, int s){
        uint32_t ao = adst + s * STG_H * 2;
        uint32_t bo = bdst + s * STG_H * 2;
        const __half* ag = Ap + c * 32;
        const __half* bg = Bp + c * 32;
        CPA16(ao, ag); CPA16(ao + 16, ag + 8);
        CPA16(bo, bg); CPA16(bo + 16, bg + 8);
        asm volatile("cp.async.commit_group;" ::: "memory");
    };

    float acc[4][4][4] = {};

    const int a_row = lane & 15;
    const int a_col = (lane >> 4) * 8;
    const int b_row = (lane & 7) + ((lane >> 4) << 3);
    const int b_col = ((lane >> 3) & 1) * 8;

    auto compute = [&](int s){
        const __half* Ab = As + s * STG_H;
        const __half* Bb2 = Bs + s * STG_H;
        #pragma unroll
        for (int kk = 0; kk < 2; kk++){
            uint32_t afr[4][4];
            #pragma unroll
            for (int mt = 0; mt < 4; mt++){
                uint32_t addr = (uint32_t)__cvta_generic_to_shared(
                    &Ab[(warpM + mt*16 + a_row) * HSTR + kk*16 + a_col]);
                asm volatile("ldmatrix.sync.aligned.m8n8.x4.shared.b16 {%0,%1,%2,%3}, [%4];"
                    : "=r"(afr[mt][0]), "=r"(afr[mt][1]), "=r"(afr[mt][2]), "=r"(afr[mt][3])
                    : "r"(addr));
            }
            uint32_t bfr[2][4];
            #pragma unroll
            for (int ng = 0; ng < 2; ng++){
                uint32_t addr = (uint32_t)__cvta_generic_to_shared(
                    &Bb2[(warpN + ng*16 + b_row) * HSTR + kk*16 + b_col]);
                asm volatile("ldmatrix.sync.aligned.m8n8.x4.shared.b16 {%0,%1,%2,%3}, [%4];"
                    : "=r"(bfr[ng][0]), "=r"(bfr[ng][1]), "=r"(bfr[ng][2]), "=r"(bfr[ng][3])
                    : "r"(addr));
            }
            #pragma unroll
            for (int mt = 0; mt < 4; mt++)
                #pragma unroll
                for (int nt = 0; nt < 4; nt++){
                    uint32_t b0 = bfr[nt >> 1][(nt & 1) * 2];
                    uint32_t b1 = bfr[nt >> 1][(nt & 1) * 2 + 1];
                    asm volatile(
                        "mma.sync.aligned.m16n8k16.row.col.f32.f16.f16.f32 "
                        "{%0,%1,%2,%3},{%4,%5,%6,%7},{%8,%9},{%0,%1,%2,%3};"
                        : "+f"(acc[mt][nt][0]), "+f"(acc[mt][nt][1]),
                          "+f"(acc[mt][nt][2]), "+f"(acc[mt][nt][3])
                        : "r"(afr[mt][0]), "r"(afr[mt][1]), "r"(afr[mt][2]), "r"(afr[mt][3]),
                          "r"(b0), "r"(b1));
                }
        }
    };

    const int ntiles = K / 32;
    load_chunk(0, 0); load_chunk(1, 1); load_chunk(2, 2); load_chunk(3, 3);
    int s = 0, sl = 4;
    for (int t = 0; t < ntiles; t++){
        int pend = ntiles - 1 - t;
        if (pend >= 3)      asm volatile("cp.async.wait_group 3;" ::: "memory");
        else if (pend == 2) asm volatile("cp.async.wait_group 2;" ::: "memory");
        else if (pend == 1) asm volatile("cp.async.wait_group 1;" ::: "memory");
        else                asm volatile("cp.async.wait_group 0;" ::: "memory");
        __syncthreads();
        if (t + 4 < ntiles){
            load_chunk(t + 4, sl);
            if (++sl == NSTG) sl = 0;
        }
        compute(s);
        if (++s == NSTG) s = 0;
    }

    #pragma unroll
    for (int mt = 0; mt < 4; mt++){
        #pragma unroll
        for (int nt = 0; nt < 4; nt++){
            int rr = row0 + warpM + mt*16 + (lane >> 2);
            int cc = col0 + warpN + nt*8 + (lane & 3) * 2;
            #pragma unroll
            for (int half = 0; half < 2; half++){
                int r = rr + half * 8;
                float v0 = acc[mt][nt][half*2]     + bias[cc];
                float v1 = acc[mt][nt][half*2 + 1] + bias[cc + 1];
                if (resid){
                    const float2 rv = *(const float2*)&resid[(size_t)r * N + cc];
                    v0 += rv.x; v1 += rv.y;
                }
                if (do_gelu){
                    v0 = 0.5f * v0 * (1.f + erff(v0 * 0.70710678118f));
                    v1 = 0.5f * v1 * (1.f + erff(v1 * 0.70710678118f));
                }
                if (OUT_HALF){
                    *(__half2*)&((__half*)outv)[(size_t)r * N + cc] = __floats2half2_rn(v0, v1);
                } else {
                    *(float2*)&((float*)outv)[(size_t)r * N + cc] = make_float2(v0, v1);
                }
            }
        }
    }
}

// ======================== Attention: R12 (full 64-key tiles, log2 LIF) ========================
#define HQ 72
#define QVLD (2*Cc)
#define ATTN_SMEM ((128 + 128 + 128) * HQ * 2)

__device__ __forceinline__ float rcp_a(float x){ float r; asm("rcp.approx.f32 %0,%1;" : "=f"(r) : "f"(x)); return r; }
__device__ __forceinline__ float lg2_a(float x){ float r; asm("lg2.approx.f32 %0,%1;" : "=f"(r) : "f"(x)); return r; }
__device__ __forceinline__ float ex2_a(float x){ float r; asm("ex2.approx.f32 %0,%1;" : "=f"(r) : "f"(x)); return r; }

__device__ __forceinline__ float lif_s2(float I){
    float u  = rcp_a(I);
    float wv = 1.0f - u;
    float lg = lg2_a(wv);
    float dd = fmaf(lg, -0.0138629436112f, 0.002f);
    float s2 = rcp_a(dd) * 0.180336879f;
    return (I > 1.0000001f) ? s2 : 0.0f;
}

__global__ __launch_bounds__(256) void attn_tc(
        const __half* __restrict__ Q, const __half* __restrict__ V,
        const __half* __restrict__ EH, const float* __restrict__ gain,
        const float* __restrict__ bias, __half* __restrict__ out){
    extern __shared__ __half smh[];
    __half* PsH = smh;
    __half* EsH = smh + 128*HQ;
    __half* VsH = smh + (128 + 128)*HQ;

    const int tid = threadIdx.x;
    const int lane = tid & 31, w = tid >> 5;
    const int bh = blockIdx.y, b = bh >> 4, h = bh & 15;
    const int t0 = (gridDim.x - 1 - blockIdx.x) << 7;
    const int rowbase = w << 4;

    const int a_row = lane & 15;
    const int a_col = (lane >> 4) * 8;
    const int b_row = (lane & 7) + ((lane >> 4) << 3);
    const int b_col = ((lane >> 3) & 1) * 8;
    const int v_row = (lane & 7) + ((lane >> 3) & 1) * 8;
    const int v_col = (lane >> 4) * 8;

    {
        const int qr = tid >> 1, qc = (tid & 1) * 32;
        const __half* qp = Q + ((size_t)(b*Tt + t0 + qr)) * QVLD + h*Dd + qc;
        #pragma unroll
        for (int j = 0; j < 4; j++)
            *(uint4*)&PsH[qr*HQ + qc + j*8] = *(const uint4*)(qp + j*8);
    }
    __syncthreads();

    uint32_t qa[4][4];
    #pragma unroll
    for (int kk = 0; kk < 4; kk++){
        uint32_t addr = (uint32_t)__cvta_generic_to_shared(
            &PsH[(rowbase + a_row) * HQ + kk*16 + a_col]);
        asm volatile("ldmatrix.sync.aligned.m8n8.x4.shared.b16 {%0,%1,%2,%3}, [%4];"
            : "=r"(qa[kk][0]), "=r"(qa[kk][1]), "=r"(qa[kk][2]), "=r"(qa[kk][3])
            : "r"(addr));
    }

    const int r = lane >> 2;
    const int cq = (lane & 3) << 1;
    const int tA = t0 + rowbase + r;
    const int tB = tA + 8;
    const float gA = gain[h*Tt + tA], bA = bias[h*Tt + tA];
    const float gB = gain[h*Tt + tB], bB = bias[h*Tt + tB];
    const int twmax = t0 + rowbase + 15;
    const int wmin  = t0 + rowbase;

    float oacc[8][4] = {};
    float psumA = 0.f, psumB = 0.f;
    float mA = 0.f, mB = 0.f;

    const int s_lr = tid >> 2;
    const int s_ck = (tid & 3) * 16;
    auto stage_tile = [&](int s0, int sbuf){
        const __half* eg = EH + ((size_t)(h*Tt + s0 + s_lr)) * Dd + s_ck;
        uint32_t ed = (uint32_t)__cvta_generic_to_shared(&EsH[sbuf*64*HQ + s_lr*HQ + s_ck]);
        CPA16(ed, eg); CPA16(ed + 16, eg + 8);
        const __half* vg = V + ((size_t)(b*Tt + s0 + s_lr)) * QVLD + h*Dd + s_ck;
        uint32_t vd = (uint32_t)__cvta_generic_to_shared(&VsH[sbuf*64*HQ + s_lr*HQ + s_ck]);
        CPA16(vd, vg); CPA16(vd + 16, vg + 8);
        asm volatile("cp.async.commit_group;" ::: "memory");
    };

    const int nIt = (t0 >> 6) + 2;
    stage_tile(0, 0);
    int buf = 0;

    for (int it = 0; it < nIt; it++){
        const int s0 = it << 6;
        asm volatile("cp.async.wait_group 0;" ::: "memory");
        __syncthreads();
        if (it + 1 < nIt) stage_tile(s0 + 64, buf ^ 1);

        if (s0 <= twmax){
            const __half* Eb = EsH + buf*64*HQ;
            const __half* Vb = VsH + buf*64*HQ;

            float sacc[8][4] = {};
            #pragma unroll
            for (int kk = 0; kk < 4; kk++){
                uint32_t bfr[4][4];
                #pragma unroll
                for (int ng = 0; ng < 4; ng++){
                    uint32_t addr = (uint32_t)__cvta_generic_to_shared(
                        &Eb[(ng*16 + b_row) * HQ + kk*16 + b_col]);
                    asm volatile("ldmatrix.sync.aligned.m8n8.x4.shared.b16 {%0,%1,%2,%3}, [%4];"
                        : "=r"(bfr[ng][0]), "=r"(bfr[ng][1]), "=r"(bfr[ng][2]), "=r"(bfr[ng][3])
                        : "r"(addr));
                }
                #pragma unroll
                for (int nt = 0; nt < 8; nt++){
                    uint32_t b0 = bfr[nt >> 1][(nt & 1) * 2];
                    uint32_t b1 = bfr[nt >> 1][(nt & 1) * 2 + 1];
                    asm volatile(
                        "mma.sync.aligned.m16n8k16.row.col.f32.f16.f16.f32 "
                        "{%0,%1,%2,%3},{%4,%5,%6,%7},{%8,%9},{%0,%1,%2,%3};"
                        : "+f"(sacc[nt][0]), "+f"(sacc[nt][1]),
                          "+f"(sacc[nt][2]), "+f"(sacc[nt][3])
                        : "r"(qa[kk][0]), "r"(qa[kk][1]), "r"(qa[kk][2]), "r"(qa[kk][3]),
                          "r"(b0), "r"(b1));
                }
            }

            float tmaxA = 0.f, tmaxB = 0.f;
            if (s0 + 63 <= wmin){
                #pragma unroll
                for (int nt = 0; nt < 8; nt++){
                    float v00 = lif_s2(fmaf(gA, sacc[nt][0], bA));
                    float v01 = lif_s2(fmaf(gA, sacc[nt][1], bA));
                    float v10 = lif_s2(fmaf(gB, sacc[nt][2], bB));
                    float v11 = lif_s2(fmaf(gB, sacc[nt][3], bB));
                    sacc[nt][0] = v00; sacc[nt][1] = v01; sacc[nt][2] = v10; sacc[nt][3] = v11;
                    tmaxA = fmaxf(tmaxA, fmaxf(v00, v01));
                    tmaxB = fmaxf(tmaxB, fmaxf(v10, v11));
                }
            } else {
                #pragma unroll
                for (int nt = 0; nt < 8; nt++){
                    int sb = s0 + nt*8 + cq;
                    float v00 = (sb     <= tA) ? lif_s2(fmaf(gA, sacc[nt][0], bA)) : -1e30f;
                    float v01 = (sb + 1 <= tA) ? lif_s2(fmaf(gA, sacc[nt][1], bA)) : -1e30f;
                    float v10 = (sb     <= tB) ? lif_s2(fmaf(gB, sacc[nt][2], bB)) : -1e30f;
                    float v11 = (sb + 1 <= tB) ? lif_s2(fmaf(gB, sacc[nt][3], bB)) : -1e30f;
                    sacc[nt][0] = v00; sacc[nt][1] = v01; sacc[nt][2] = v10; sacc[nt][3] = v11;
                    tmaxA = fmaxf(tmaxA, fmaxf(v00, v01));
                    tmaxB = fmaxf(tmaxB, fmaxf(v10, v11));
                }
            }
            tmaxA = fmaxf(tmaxA, __shfl_xor_sync(0xffffffffu, tmaxA, 1));
            tmaxA = fmaxf(tmaxA, __shfl_xor_sync(0xffffffffu, tmaxA, 2));
            tmaxB = fmaxf(tmaxB, __shfl_xor_sync(0xffffffffu, tmaxB, 1));
            tmaxB = fmaxf(tmaxB, __shfl_xor_sync(0xffffffffu, tmaxB, 2));

            if (__any_sync(0xffffffffu, (tmaxA > mA) || (tmaxB > mB))){
                float mAn = fmaxf(mA, tmaxA), mBn = fmaxf(mB, tmaxB);
                float scA = ex2_a(mA - mAn), scB = ex2_a(mB - mBn);
                mA = mAn; mB = mBn;
                psumA *= scA; psumB *= scB;
                #pragma unroll
                for (int nt = 0; nt < 8; nt++){
                    oacc[nt][0] *= scA; oacc[nt][1] *= scA;
                    oacc[nt][2] *= scB; oacc[nt][3] *= scB;
                }
            }

            uint32_t pa[4][4];
            #pragma unroll
            for (int nt = 0; nt < 8; nt++){
                float p00 = ex2_a(sacc[nt][0] - mA);
                float p01 = ex2_a(sacc[nt][1] - mA);
                float p10 = ex2_a(sacc[nt][2] - mB);
                float p11 = ex2_a(sacc[nt][3] - mB);
                psumA += p00 + p01;
                psumB += p10 + p11;
                __half2 hA = __floats2half2_rn(p00, p01);
                __half2 hB = __floats2half2_rn(p10, p11);
                pa[nt >> 1][(nt & 1) * 2    ] = *(uint32_t*)&hA;
                pa[nt >> 1][(nt & 1) * 2 + 1] = *(uint32_t*)&hB;
            }

            #pragma unroll
            for (int kk = 0; kk < 4; kk++){
                uint32_t bfr[4][4];
                #pragma unroll
                for (int ng = 0; ng < 4; ng++){
                    uint32_t addr = (uint32_t)__cvta_generic_to_shared(
                        &Vb[(kk*16 + v_row) * HQ + ng*16 + v_col]);
                    asm volatile("ldmatrix.sync.aligned.m8n8.x4.trans.shared.b16 {%0,%1,%2,%3}, [%4];"
                        : "=r"(bfr[ng][0]), "=r"(bfr[ng][1]), "=r"(bfr[ng][2]), "=r"(bfr[ng][3])
                        : "r"(addr));
                }
                #pragma unroll
                for (int nt = 0; nt < 8; nt++){
                    uint32_t b0 = bfr[nt >> 1][(nt & 1) * 2];
                    uint32_t b1 = bfr[nt >> 1][(nt & 1) * 2 + 1];
                    asm volatile(
                        "mma.sync.aligned.m16n8k16.row.col.f32.f16.f16.f32 "
                        "{%0,%1,%2,%3},{%4,%5,%6,%7},{%8,%9},{%0,%1,%2,%3};"
                        : "+f"(oacc[nt][0]), "+f"(oacc[nt][1]),
                          "+f"(oacc[nt][2]), "+f"(oacc[nt][3])
                        : "r"(pa[kk][0]), "r"(pa[kk][1]), "r"(pa[kk][2]), "r"(pa[kk][3]),
                          "r"(b0), "r"(b1));
                }
            }
        }
        buf ^= 1;
    }

    psumA += __shfl_xor_sync(0xffffffffu, psumA, 1);
    psumA += __shfl_xor_sync(0xffffffffu, psumA, 2);
    psumB += __shfl_xor_sync(0xffffffffu, psumB, 1);
    psumB += __shfl_xor_sync(0xffffffffu, psumB, 2);
    float invA = 1.0f / psumA;
    float invB = 1.0f / psumB;

    __half* opA = out + ((size_t)(b*Tt + tA)) * Cc + h*Dd;
    __half* opB = out + ((size_t)(b*Tt + tB)) * Cc + h*Dd;
    #pragma unroll
    for (int nt = 0; nt < 8; nt++){
        int d = nt*8 + cq;
        *(__half2*)&opA[d] = __floats2half2_rn(oacc[nt][0]*invA, oacc[nt][1]*invA);
        *(__half2*)&opB[d] = __floats2half2_rn(oacc[nt][2]*invB, oacc[nt][3]*invB);
    }
}

// ======================== launch ========================
extern "C" void kernel_launch(void* const* d_in, const int* in_sizes, int n_in,
                              void* d_out, int out_size){
    const float* x      = (const float*)d_in[0];
    const float* ln1_g  = (const float*)d_in[1];
    const float* ln1_b  = (const float*)d_in[2];
    const float* qkv_w  = (const float*)d_in[3];
    const float* qkv_b  = (const float*)d_in[4];
    const float* out_w  = (const float*)d_in[5];
    const float* out_b  = (const float*)d_in[6];
    const float* ln2_g  = (const float*)d_in[7];
    const float* ln2_b  = (const float*)d_in[8];
    const float* mlp_w1 = (const float*)d_in[9];
    const float* mlp_b1 = (const float*)d_in[10];
    const float* mlp_w2 = (const float*)d_in[11];
    const float* mlp_b2 = (const float*)d_in[12];
    const float* enc    = (const float*)d_in[13];
    const float* gain   = (const float*)d_in[14];
    const float* battn  = (const float*)d_in[15];
    float* outp = (float*)d_out;

    __half *xn, *qv, *att, *hbuf, *wqv, *wo, *w1, *w2, *eh;
    float *x1, *qvb;
    cudaGetSymbolAddress((void**)&xn,   g_xn);
    cudaGetSymbolAddress((void**)&qv,   g_qv);
    cudaGetSymbolAddress((void**)&att,  g_att);
    cudaGetSymbolAddress((void**)&x1,   g_x1);
    cudaGetSymbolAddress((void**)&hbuf, g_h);
    cudaGetSymbolAddress((void**)&wqv,  g_wqv);
    cudaGetSymbolAddress((void**)&wo,   g_wo);
    cudaGetSymbolAddress((void**)&w1,   g_w1);
    cudaGetSymbolAddress((void**)&w2,   g_w2);
    cudaGetSymbolAddress((void**)&qvb,  g_qvb);
    cudaGetSymbolAddress((void**)&eh,   g_eh);

    cudaFuncSetAttribute(attn_tc,       cudaFuncAttributeMaxDynamicSharedMemorySize, ATTN_SMEM);
    cudaFuncSetAttribute(gemm_h<true>,  cudaFuncAttributeMaxDynamicSharedMemorySize, GH_SMEM);
    cudaFuncSetAttribute(gemm_h<false>, cudaFuncAttributeMaxDynamicSharedMemorySize, GH_SMEM);

    const int M = Bb * Tt;

    prep_all<<<12296, dim3(32,8)>>>(qkv_w, out_w, mlp_w1, mlp_w2, qkv_b, enc,
                                    wqv, wo, w1, w2, qvb, eh);

    ln_kernel<<<M, 256>>>(x, ln1_g, ln1_b, xn);
    gemm_h<true ><<<dim3(2*Cc/128, M/128), 256, GH_SMEM>>>(xn, wqv, qvb, nullptr, qv, 2*Cc, Cc, 0);
    attn_tc<<<dim3(Tt/128, Bb*Hh), 256, ATTN_SMEM>>>(qv, qv + Cc, eh, gain, battn, att);
    gemm_h<false><<<dim3(Cc/128, M/128), 256, GH_SMEM>>>(att, wo, out_b, x, x1, Cc, Cc, 0);
    ln_kernel<<<M, 256>>>(x1, ln2_g, ln2_b, xn);
    gemm_h<true ><<<dim3(4*Cc/128, M/128), 256, GH_SMEM>>>(xn, w1, mlp_b1, nullptr, hbuf, 4*Cc, Cc, 1);
    gemm_h<false><<<dim3(Cc/128, M/128), 256, GH_SMEM>>>(hbuf, w2, mlp_b2, x1, outp, Cc, 4*Cc, 0);
}

// round 15
// speedup vs baseline: 1.0658x; 1.0302x over previous
#include <cuda_runtime.h>
#include <cuda_fp16.h>
#include <math.h>
#include <stdint.h>

#define Bb 2
#define Tt 2048
#define Cc 1024
#define Hh 16
#define Dd 64

__device__ __half g_xn [Bb*Tt*Cc];
__device__ __half g_qv [Bb*Tt*2*Cc];
__device__ __half g_att[Bb*Tt*Cc];
__device__ float  g_x1 [Bb*Tt*Cc];
__device__ __half g_h  [Bb*Tt*4*Cc];
__device__ __half g_wqv[2*Cc*Cc];
__device__ __half g_wo [Cc*Cc];
__device__ __half g_w1 [4*Cc*Cc];
__device__ __half g_w2 [Cc*4*Cc];
__device__ float  g_qvb[2*Cc];
__device__ __half g_eh [Hh*Tt*Dd];

#define CPA16(dst, src) \
    asm volatile("cp.async.cg.shared.global [%0], [%1], 16;" :: "r"(dst), "l"(src) : "memory")

__device__ __forceinline__ float rcp_a(float x){ float r; asm("rcp.approx.f32 %0,%1;" : "=f"(r) : "f"(x)); return r; }
__device__ __forceinline__ float lg2_a(float x){ float r; asm("lg2.approx.f32 %0,%1;" : "=f"(r) : "f"(x)); return r; }
__device__ __forceinline__ float ex2_a(float x){ float r; asm("ex2.approx.f32 %0,%1;" : "=f"(r) : "f"(x)); return r; }

// tanh-form GELU via ex2/rcp: gelu(x) = x * z / (z + 1), z = exp(2*0.7978845608*(x + 0.044715 x^3))
__device__ __forceinline__ float gelu_fast(float x){
    float x2 = x * x;
    float t  = x * fmaf(x2, 0.1029413588f, 2.3021182052f);   // 2*c1*log2e * (x + 0.044715 x^3)
    float z  = ex2_a(t);
    return x * z * rcp_a(z + 1.0f);
}

// ======================== fused prep ========================
__global__ void prep_all(const float* __restrict__ qkv_w, const float* __restrict__ out_w,
                         const float* __restrict__ mlp_w1, const float* __restrict__ mlp_w2,
                         const float* __restrict__ qkv_b, const float* __restrict__ enc,
                         __half* __restrict__ wqv, __half* __restrict__ wo,
                         __half* __restrict__ w1,  __half* __restrict__ w2,
                         float* __restrict__ qvb,  __half* __restrict__ eh){
    const int id = blockIdx.x;
    const int tx = threadIdx.x, ty = threadIdx.y;
    if (id >= 12288){
        int i = (id - 12288) * 256 + ty*32 + tx;
        qvb[i] = (i < Cc) ? qkv_b[i] : qkv_b[i + Cc];
        return;
    }
    if (id >= 11264){
        int i = ((id - 11264) * 256 + ty*32 + tx) * 8;
        float4 a = *(const float4*)(enc + i);
        float4 c = *(const float4*)(enc + i + 4);
        __half2 h0 = __floats2half2_rn(a.x, a.y);
        __half2 h1 = __floats2half2_rn(a.z, a.w);
        __half2 h2 = __floats2half2_rn(c.x, c.y);
        __half2 h3 = __floats2half2_rn(c.z, c.w);
        *(uint4*)(eh + i) = make_uint4(*(uint32_t*)&h0, *(uint32_t*)&h1,
                                       *(uint32_t*)&h2, *(uint32_t*)&h3);
        return;
    }
    const float* W; __half* Wt; int ldw, K, ntn, base;
    if      (id < 1024){ W = qkv_w;          Wt = wqv;         ldw = 3*Cc; K = Cc;   ntn = 32;  base = id; }
    else if (id < 2048){ W = qkv_w + 2*Cc;   Wt = wqv + Cc*Cc; ldw = 3*Cc; K = Cc;   ntn = 32;  base = id - 1024; }
    else if (id < 3072){ W = out_w;          Wt = wo;          ldw = Cc;   K = Cc;   ntn = 32;  base = id - 2048; }
    else if (id < 7168){ W = mlp_w1;         Wt = w1;          ldw = 4*Cc; K = Cc;   ntn = 128; base = id - 3072; }
    else               { W = mlp_w2;         Wt = w2;          ldw = Cc;   K = 4*Cc; ntn = 32;  base = id - 7168; }
    const int n0 = (base % ntn) * 32, k0 = (base / ntn) * 32;
    __shared__ float t[32][33];
    #pragma unroll
    for (int i = 0; i < 4; i++)
        t[ty + i*8][tx] = W[(size_t)(k0 + ty + i*8) * ldw + n0 + tx];
    __syncthreads();
    #pragma unroll
    for (int i = 0; i < 4; i++)
        Wt[(size_t)(n0 + ty + i*8) * K + k0 + tx] = __float2half_rn(t[tx][ty + i*8]);
}

// ======================== block reduce / LayerNorm ========================
__device__ __forceinline__ float block_sum(float v, volatile float* red){
    #pragma unroll
    for (int o = 16; o; o >>= 1) v += __shfl_xor_sync(0xffffffffu, v, o);
    int lane = threadIdx.x & 31, w = threadIdx.x >> 5;
    if (lane == 0) red[w] = v;
    __syncthreads();
    if (w == 0){
        v = (lane < 8) ? red[lane] : 0.f;
        #pragma unroll
        for (int o = 4; o; o >>= 1) v += __shfl_xor_sync(0xffffffffu, v, o);
    }
    return v;
}

__global__ void ln_kernel(const float* __restrict__ x, const float* __restrict__ g,
                          const float* __restrict__ b, __half* __restrict__ out){
    __shared__ float red[8];
    __shared__ float s_mu, s_rs;
    int row = blockIdx.x, tid = threadIdx.x;
    const float4 v = ((const float4*)(x + (size_t)row * Cc))[tid];
    float s = v.x + v.y + v.z + v.w;
    s = block_sum(s, red);
    if (tid == 0) s_mu = s * (1.0f / Cc);
    __syncthreads();
    float mu = s_mu;
    float dx = v.x - mu, dy = v.y - mu, dz = v.z - mu, dw = v.w - mu;
    float sq = dx*dx + dy*dy + dz*dz + dw*dw;
    sq = block_sum(sq, red);
    if (tid == 0) s_rs = rsqrtf(sq * (1.0f / Cc) + 1e-5f);
    __syncthreads();
    float rs = s_rs;
    float4 gg = ((const float4*)g)[tid], bb = ((const float4*)b)[tid];
    __half2 h0 = __floats2half2_rn(dx * rs * gg.x + bb.x, dy * rs * gg.y + bb.y);
    __half2 h1 = __floats2half2_rn(dz * rs * gg.z + bb.z, dw * rs * gg.w + bb.w);
    __half2* op = (__half2*)(out + (size_t)row * Cc);
    op[tid*2]     = h0;
    op[tid*2 + 1] = h1;
}

// ======================== fp16 GEMM (BK=32, 4-stage cp.async — R12 proven) ========================
#define HSTR 40
#define NSTG 4
#define STG_H (128*HSTR)
#define GH_SMEM (NSTG * STG_H * 2 * 2)

template<bool OUT_HALF>
__global__ __launch_bounds__(256) void gemm_h(
        const __half* __restrict__ A,
        const __half* __restrict__ Bt,
        const float* __restrict__ bias,
        const float* __restrict__ resid,
        void* __restrict__ outv,
        int N, int K, int do_gelu){
    extern __shared__ __half smh[];
    __half* As = smh;
    __half* Bs = smh + NSTG * STG_H;
    const int tid = threadIdx.x;
    const int lane = tid & 31, w = tid >> 5;
    const int warpM = (w & 1) * 64, warpN = (w >> 1) * 32;
    const int row0 = blockIdx.y * 128, col0 = blockIdx.x * 128;

    const int sr = tid >> 1;
    const int kh = (tid & 1) * 16;
    const __half* Ap = A + (size_t)(row0 + sr) * K + kh;
    const __half* Bp = Bt + (size_t)(col0 + sr) * K + kh;
    const uint32_t adst = (uint32_t)__cvta_generic_to_shared(&As[sr*HSTR + kh]);
    const uint32_t bdst = (uint32_t)__cvta_generic_to_shared(&Bs[sr*HSTR + kh]);

    auto load_chunk = [&](int c, int s){
        uint32_t ao = adst + s * STG_H * 2;
        uint32_t bo = bdst + s * STG_H * 2;
        const __half* ag = Ap + c * 32;
        const __half* bg = Bp + c * 32;
        CPA16(ao, ag); CPA16(ao + 16, ag + 8);
        CPA16(bo, bg); CPA16(bo + 16, bg + 8);
        asm volatile("cp.async.commit_group;" ::: "memory");
    };

    float acc[4][4][4] = {};

    const int a_row = lane & 15;
    const int a_col = (lane >> 4) * 8;
    const int b_row = (lane & 7) + ((lane >> 4) << 3);
    const int b_col = ((lane >> 3) & 1) * 8;

    auto compute = [&](int s){
        const __half* Ab = As + s * STG_H;
        const __half* Bb2 = Bs + s * STG_H;
        #pragma unroll
        for (int kk = 0; kk < 2; kk++){
            uint32_t afr[4][4];
            #pragma unroll
            for (int mt = 0; mt < 4; mt++){
                uint32_t addr = (uint32_t)__cvta_generic_to_shared(
                    &Ab[(warpM + mt*16 + a_row) * HSTR + kk*16 + a_col]);
                asm volatile("ldmatrix.sync.aligned.m8n8.x4.shared.b16 {%0,%1,%2,%3}, [%4];"
                    : "=r"(afr[mt][0]), "=r"(afr[mt][1]), "=r"(afr[mt][2]), "=r"(afr[mt][3])
                    : "r"(addr));
            }
            uint32_t bfr[2][4];
            #pragma unroll
            for (int ng = 0; ng < 2; ng++){
                uint32_t addr = (uint32_t)__cvta_generic_to_shared(
                    &Bb2[(warpN + ng*16 + b_row) * HSTR + kk*16 + b_col]);
                asm volatile("ldmatrix.sync.aligned.m8n8.x4.shared.b16 {%0,%1,%2,%3}, [%4];"
                    : "=r"(bfr[ng][0]), "=r"(bfr[ng][1]), "=r"(bfr[ng][2]), "=r"(bfr[ng][3])
                    : "r"(addr));
            }
            #pragma unroll
            for (int mt = 0; mt < 4; mt++)
                #pragma unroll
                for (int nt = 0; nt < 4; nt++){
                    uint32_t b0 = bfr[nt >> 1][(nt & 1) * 2];
                    uint32_t b1 = bfr[nt >> 1][(nt & 1) * 2 + 1];
                    asm volatile(
                        "mma.sync.aligned.m16n8k16.row.col.f32.f16.f16.f32 "
                        "{%0,%1,%2,%3},{%4,%5,%6,%7},{%8,%9},{%0,%1,%2,%3};"
                        : "+f"(acc[mt][nt][0]), "+f"(acc[mt][nt][1]),
                          "+f"(acc[mt][nt][2]), "+f"(acc[mt][nt][3])
                        : "r"(afr[mt][0]), "r"(afr[mt][1]), "r"(afr[mt][2]), "r"(afr[mt][3]),
                          "r"(b0), "r"(b1));
                }
        }
    };

    const int ntiles = K / 32;
    load_chunk(0, 0); load_chunk(1, 1); load_chunk(2, 2);
    for (int t = 0; t < ntiles; t++){
        asm volatile("cp.async.wait_group 2;" ::: "memory");
        __syncthreads();
        if (t + 3 < ntiles) load_chunk(t + 3, (t + 3) & 3);
        compute(t & 3);
    }

    #pragma unroll
    for (int mt = 0; mt < 4; mt++){
        #pragma unroll
        for (int nt = 0; nt < 4; nt++){
            int rr = row0 + warpM + mt*16 + (lane >> 2);
            int cc = col0 + warpN + nt*8 + (lane & 3) * 2;
            #pragma unroll
            for (int half = 0; half < 2; half++){
                int r = rr + half * 8;
                float v0 = acc[mt][nt][half*2]     + bias[cc];
                float v1 = acc[mt][nt][half*2 + 1] + bias[cc + 1];
                if (resid){
                    const float2 rv = *(const float2*)&resid[(size_t)r * N + cc];
                    v0 += rv.x; v1 += rv.y;
                }
                if (do_gelu){
                    v0 = gelu_fast(v0);
                    v1 = gelu_fast(v1);
                }
                if (OUT_HALF){
                    *(__half2*)&((__half*)outv)[(size_t)r * N + cc] = __floats2half2_rn(v0, v1);
                } else {
                    *(float2*)&((float*)outv)[(size_t)r * N + cc] = make_float2(v0, v1);
                }
            }
        }
    }
}

// ======================== Attention: R12 (full 64-key tiles, log2 LIF) ========================
#define HQ 72
#define QVLD (2*Cc)
#define ATTN_SMEM ((128 + 128 + 128) * HQ * 2)

__device__ __forceinline__ float lif_s2(float I){
    float u  = rcp_a(I);
    float wv = 1.0f - u;
    float lg = lg2_a(wv);
    float dd = fmaf(lg, -0.0138629436112f, 0.002f);
    float s2 = rcp_a(dd) * 0.180336879f;
    return (I > 1.0000001f) ? s2 : 0.0f;
}

__global__ __launch_bounds__(256) void attn_tc(
        const __half* __restrict__ Q, const __half* __restrict__ V,
        const __half* __restrict__ EH, const float* __restrict__ gain,
        const float* __restrict__ bias, __half* __restrict__ out){
    extern __shared__ __half smh[];
    __half* PsH = smh;
    __half* EsH = smh + 128*HQ;
    __half* VsH = smh + (128 + 128)*HQ;

    const int tid = threadIdx.x;
    const int lane = tid & 31, w = tid >> 5;
    const int bh = blockIdx.y, b = bh >> 4, h = bh & 15;
    const int t0 = (gridDim.x - 1 - blockIdx.x) << 7;
    const int rowbase = w << 4;

    const int a_row = lane & 15;
    const int a_col = (lane >> 4) * 8;
    const int b_row = (lane & 7) + ((lane >> 4) << 3);
    const int b_col = ((lane >> 3) & 1) * 8;
    const int v_row = (lane & 7) + ((lane >> 3) & 1) * 8;
    const int v_col = (lane >> 4) * 8;

    {
        const int qr = tid >> 1, qc = (tid & 1) * 32;
        const __half* qp = Q + ((size_t)(b*Tt + t0 + qr)) * QVLD + h*Dd + qc;
        #pragma unroll
        for (int j = 0; j < 4; j++)
            *(uint4*)&PsH[qr*HQ + qc + j*8] = *(const uint4*)(qp + j*8);
    }
    __syncthreads();

    uint32_t qa[4][4];
    #pragma unroll
    for (int kk = 0; kk < 4; kk++){
        uint32_t addr = (uint32_t)__cvta_generic_to_shared(
            &PsH[(rowbase + a_row) * HQ + kk*16 + a_col]);
        asm volatile("ldmatrix.sync.aligned.m8n8.x4.shared.b16 {%0,%1,%2,%3}, [%4];"
            : "=r"(qa[kk][0]), "=r"(qa[kk][1]), "=r"(qa[kk][2]), "=r"(qa[kk][3])
            : "r"(addr));
    }

    const int r = lane >> 2;
    const int cq = (lane & 3) << 1;
    const int tA = t0 + rowbase + r;
    const int tB = tA + 8;
    const float gA = gain[h*Tt + tA], bA = bias[h*Tt + tA];
    const float gB = gain[h*Tt + tB], bB = bias[h*Tt + tB];
    const int twmax = t0 + rowbase + 15;
    const int wmin  = t0 + rowbase;

    float oacc[8][4] = {};
    float psumA = 0.f, psumB = 0.f;
    float mA = 0.f, mB = 0.f;

    const int s_lr = tid >> 2;
    const int s_ck = (tid & 3) * 16;
    auto stage_tile = [&](int s0, int sbuf){
        const __half* eg = EH + ((size_t)(h*Tt + s0 + s_lr)) * Dd + s_ck;
        uint32_t ed = (uint32_t)__cvta_generic_to_shared(&EsH[sbuf*64*HQ + s_lr*HQ + s_ck]);
        CPA16(ed, eg); CPA16(ed + 16, eg + 8);
        const __half* vg = V + ((size_t)(b*Tt + s0 + s_lr)) * QVLD + h*Dd + s_ck;
        uint32_t vd = (uint32_t)__cvta_generic_to_shared(&VsH[sbuf*64*HQ + s_lr*HQ + s_ck]);
        CPA16(vd, vg); CPA16(vd + 16, vg + 8);
        asm volatile("cp.async.commit_group;" ::: "memory");
    };

    const int nIt = (t0 >> 6) + 2;
    stage_tile(0, 0);
    int buf = 0;

    for (int it = 0; it < nIt; it++){
        const int s0 = it << 6;
        asm volatile("cp.async.wait_group 0;" ::: "memory");
        __syncthreads();
        if (it + 1 < nIt) stage_tile(s0 + 64, buf ^ 1);

        if (s0 <= twmax){
            const __half* Eb = EsH + buf*64*HQ;
            const __half* Vb = VsH + buf*64*HQ;

            float sacc[8][4] = {};
            #pragma unroll
            for (int kk = 0; kk < 4; kk++){
                uint32_t bfr[4][4];
                #pragma unroll
                for (int ng = 0; ng < 4; ng++){
                    uint32_t addr = (uint32_t)__cvta_generic_to_shared(
                        &Eb[(ng*16 + b_row) * HQ + kk*16 + b_col]);
                    asm volatile("ldmatrix.sync.aligned.m8n8.x4.shared.b16 {%0,%1,%2,%3}, [%4];"
                        : "=r"(bfr[ng][0]), "=r"(bfr[ng][1]), "=r"(bfr[ng][2]), "=r"(bfr[ng][3])
                        : "r"(addr));
                }
                #pragma unroll
                for (int nt = 0; nt < 8; nt++){
                    uint32_t b0 = bfr[nt >> 1][(nt & 1) * 2];
                    uint32_t b1 = bfr[nt >> 1][(nt & 1) * 2 + 1];
                    asm volatile(
                        "mma.sync.aligned.m16n8k16.row.col.f32.f16.f16.f32 "
                        "{%0,%1,%2,%3},{%4,%5,%6,%7},{%8,%9},{%0,%1,%2,%3};"
                        : "+f"(sacc[nt][0]), "+f"(sacc[nt][1]),
                          "+f"(sacc[nt][2]), "+f"(sacc[nt][3])
                        : "r"(qa[kk][0]), "r"(qa[kk][1]), "r"(qa[kk][2]), "r"(qa[kk][3]),
                          "r"(b0), "r"(b1));
                }
            }

            float tmaxA = 0.f, tmaxB = 0.f;
            if (s0 + 63 <= wmin){
                #pragma unroll
                for (int nt = 0; nt < 8; nt++){
                    float v00 = lif_s2(fmaf(gA, sacc[nt][0], bA));
                    float v01 = lif_s2(fmaf(gA, sacc[nt][1], bA));
                    float v10 = lif_s2(fmaf(gB, sacc[nt][2], bB));
                    float v11 = lif_s2(fmaf(gB, sacc[nt][3], bB));
                    sacc[nt][0] = v00; sacc[nt][1] = v01; sacc[nt][2] = v10; sacc[nt][3] = v11;
                    tmaxA = fmaxf(tmaxA, fmaxf(v00, v01));
                    tmaxB = fmaxf(tmaxB, fmaxf(v10, v11));
                }
            } else {
                #pragma unroll
                for (int nt = 0; nt < 8; nt++){
                    int sb = s0 + nt*8 + cq;
                    float v00 = (sb     <= tA) ? lif_s2(fmaf(gA, sacc[nt][0], bA)) : -1e30f;
                    float v01 = (sb + 1 <= tA) ? lif_s2(fmaf(gA, sacc[nt][1], bA)) : -1e30f;
                    float v10 = (sb     <= tB) ? lif_s2(fmaf(gB, sacc[nt][2], bB)) : -1e30f;
                    float v11 = (sb + 1 <= tB) ? lif_s2(fmaf(gB, sacc[nt][3], bB)) : -1e30f;
                    sacc[nt][0] = v00; sacc[nt][1] = v01; sacc[nt][2] = v10; sacc[nt][3] = v11;
                    tmaxA = fmaxf(tmaxA, fmaxf(v00, v01));
                    tmaxB = fmaxf(tmaxB, fmaxf(v10, v11));
                }
            }
            tmaxA = fmaxf(tmaxA, __shfl_xor_sync(0xffffffffu, tmaxA, 1));
            tmaxA = fmaxf(tmaxA, __shfl_xor_sync(0xffffffffu, tmaxA, 2));
            tmaxB = fmaxf(tmaxB, __shfl_xor_sync(0xffffffffu, tmaxB, 1));
            tmaxB = fmaxf(tmaxB, __shfl_xor_sync(0xffffffffu, tmaxB, 2));

            if (__any_sync(0xffffffffu, (tmaxA > mA) || (tmaxB > mB))){
                float mAn = fmaxf(mA, tmaxA), mBn = fmaxf(mB, tmaxB);
                float scA = ex2_a(mA - mAn), scB = ex2_a(mB - mBn);
                mA = mAn; mB = mBn;
                psumA *= scA; psumB *= scB;
                #pragma unroll
                for (int nt = 0; nt < 8; nt++){
                    oacc[nt][0] *= scA; oacc[nt][1] *= scA;
                    oacc[nt][2] *= scB; oacc[nt][3] *= scB;
                }
            }

            uint32_t pa[4][4];
            #pragma unroll
            for (int nt = 0; nt < 8; nt++){
                float p00 = ex2_a(sacc[nt][0] - mA);
                float p01 = ex2_a(sacc[nt][1] - mA);
                float p10 = ex2_a(sacc[nt][2] - mB);
                float p11 = ex2_a(sacc[nt][3] - mB);
                psumA += p00 + p01;
                psumB += p10 + p11;
                __half2 hA = __floats2half2_rn(p00, p01);
                __half2 hB = __floats2half2_rn(p10, p11);
                pa[nt >> 1][(nt & 1) * 2    ] = *(uint32_t*)&hA;
                pa[nt >> 1][(nt & 1) * 2 + 1] = *(uint32_t*)&hB;
            }

            #pragma unroll
            for (int kk = 0; kk < 4; kk++){
                uint32_t bfr[4][4];
                #pragma unroll
                for (int ng = 0; ng < 4; ng++){
                    uint32_t addr = (uint32_t)__cvta_generic_to_shared(
                        &Vb[(kk*16 + v_row) * HQ + ng*16 + v_col]);
                    asm volatile("ldmatrix.sync.aligned.m8n8.x4.trans.shared.b16 {%0,%1,%2,%3}, [%4];"
                        : "=r"(bfr[ng][0]), "=r"(bfr[ng][1]), "=r"(bfr[ng][2]), "=r"(bfr[ng][3])
                        : "r"(addr));
                }
                #pragma unroll
                for (int nt = 0; nt < 8; nt++){
                    uint32_t b0 = bfr[nt >> 1][(nt & 1) * 2];
                    uint32_t b1 = bfr[nt >> 1][(nt & 1) * 2 + 1];
                    asm volatile(
                        "mma.sync.aligned.m16n8k16.row.col.f32.f16.f16.f32 "
                        "{%0,%1,%2,%3},{%4,%5,%6,%7},{%8,%9},{%0,%1,%2,%3};"
                        : "+f"(oacc[nt][0]), "+f"(oacc[nt][1]),
                          "+f"(oacc[nt][2]), "+f"(oacc[nt][3])
                        : "r"(pa[kk][0]), "r"(pa[kk][1]), "r"(pa[kk][2]), "r"(pa[kk][3]),
                          "r"(b0), "r"(b1));
                }
            }
        }
        buf ^= 1;
    }

    psumA += __shfl_xor_sync(0xffffffffu, psumA, 1);
    psumA += __shfl_xor_sync(0xffffffffu, psumA, 2);
    psumB += __shfl_xor_sync(0xffffffffu, psumB, 1);
    psumB += __shfl_xor_sync(0xffffffffu, psumB, 2);
    float invA = 1.0f / psumA;
    float invB = 1.0f / psumB;

    __half* opA = out + ((size_t)(b*Tt + tA)) * Cc + h*Dd;
    __half* opB = out + ((size_t)(b*Tt + tB)) * Cc + h*Dd;
    #pragma unroll
    for (int nt = 0; nt < 8; nt++){
        int d = nt*8 + cq;
        *(__half2*)&opA[d] = __floats2half2_rn(oacc[nt][0]*invA, oacc[nt][1]*invA);
        *(__half2*)&opB[d] = __floats2half2_rn(oacc[nt][2]*invB, oacc[nt][3]*invB);
    }
}

// ======================== launch ========================
extern "C" void kernel_launch(void* const* d_in, const int* in_sizes, int n_in,
                              void* d_out, int out_size){
    const float* x      = (const float*)d_in[0];
    const float* ln1_g  = (const float*)d_in[1];
    const float* ln1_b  = (const float*)d_in[2];
    const float* qkv_w  = (const float*)d_in[3];
    const float* qkv_b  = (const float*)d_in[4];
    const float* out_w  = (const float*)d_in[5];
    const float* out_b  = (const float*)d_in[6];
    const float* ln2_g  = (const float*)d_in[7];
    const float* ln2_b  = (const float*)d_in[8];
    const float* mlp_w1 = (const float*)d_in[9];
    const float* mlp_b1 = (const float*)d_in[10];
    const float* mlp_w2 = (const float*)d_in[11];
    const float* mlp_b2 = (const float*)d_in[12];
    const float* enc    = (const float*)d_in[13];
    const float* gain   = (const float*)d_in[14];
    const float* battn  = (const float*)d_in[15];
    float* outp = (float*)d_out;

    __half *xn, *qv, *att, *hbuf, *wqv, *wo, *w1, *w2, *eh;
    float *x1, *qvb;
    cudaGetSymbolAddress((void**)&xn,   g_xn);
    cudaGetSymbolAddress((void**)&qv,   g_qv);
    cudaGetSymbolAddress((void**)&att,  g_att);
    cudaGetSymbolAddress((void**)&x1,   g_x1);
    cudaGetSymbolAddress((void**)&hbuf, g_h);
    cudaGetSymbolAddress((void**)&wqv,  g_wqv);
    cudaGetSymbolAddress((void**)&wo,   g_wo);
    cudaGetSymbolAddress((void**)&w1,   g_w1);
    cudaGetSymbolAddress((void**)&w2,   g_w2);
    cudaGetSymbolAddress((void**)&qvb,  g_qvb);
    cudaGetSymbolAddress((void**)&eh,   g_eh);

    cudaFuncSetAttribute(attn_tc,       cudaFuncAttributeMaxDynamicSharedMemorySize, ATTN_SMEM);
    cudaFuncSetAttribute(gemm_h<true>,  cudaFuncAttributeMaxDynamicSharedMemorySize, GH_SMEM);
    cudaFuncSetAttribute(gemm_h<false>, cudaFuncAttributeMaxDynamicSharedMemorySize, GH_SMEM);

    const int M = Bb * Tt;

    prep_all<<<12296, dim3(32,8)>>>(qkv_w, out_w, mlp_w1, mlp_w2, qkv_b, enc,
                                    wqv, wo, w1, w2, qvb, eh);

    ln_kernel<<<M, 256>>>(x, ln1_g, ln1_b, xn);
    gemm_h<true ><<<dim3(2*Cc/128, M/128), 256, GH_SMEM>>>(xn, wqv, qvb, nullptr, qv, 2*Cc, Cc, 0);
    attn_tc<<<dim3(Tt/128, Bb*Hh), 256, ATTN_SMEM>>>(qv, qv + Cc, eh, gain, battn, att);
    gemm_h<false><<<dim3(Cc/128, M/128), 256, GH_SMEM>>>(att, wo, out_b, x, x1, Cc, Cc, 0);
    ln_kernel<<<M, 256>>>(x1, ln2_g, ln2_b, xn);
    gemm_h<true ><<<dim3(4*Cc/128, M/128), 256, GH_SMEM>>>(xn, w1, mlp_b1, nullptr, hbuf, 4*Cc, Cc, 1);
    gemm_h<false><<<dim3(Cc/128, M/128), 256, GH_SMEM>>>(hbuf, w2, mlp_b2, x1, outp, Cc, 4*Cc, 0);
}

// round 16
// speedup vs baseline: 1.0728x; 1.0065x over previous
#include <cuda_runtime.h>
#include <cuda_fp16.h>
#include <math.h>
#include <stdint.h>

#define Bb 2
#define Tt 2048
#define Cc 1024
#define Hh 16
#define Dd 64

__device__ __half g_xn [Bb*Tt*Cc];
__device__ __half g_qv [Bb*Tt*2*Cc];
__device__ __half g_att[Bb*Tt*Cc];
__device__ float  g_x1 [Bb*Tt*Cc];
__device__ __half g_h  [Bb*Tt*4*Cc];
__device__ __half g_wqv[2*Cc*Cc];
__device__ __half g_wo [Cc*Cc];
__device__ __half g_w1 [4*Cc*Cc];
__device__ __half g_w2 [Cc*4*Cc];
__device__ float  g_qvb[2*Cc];
__device__ __half g_eh [Hh*Tt*Dd];

#define CPA16(dst, src) \
    asm volatile("cp.async.cg.shared.global [%0], [%1], 16;" :: "r"(dst), "l"(src) : "memory")

__device__ __forceinline__ float rcp_a(float x){ float r; asm("rcp.approx.f32 %0,%1;" : "=f"(r) : "f"(x)); return r; }
__device__ __forceinline__ float lg2_a(float x){ float r; asm("lg2.approx.f32 %0,%1;" : "=f"(r) : "f"(x)); return r; }
__device__ __forceinline__ float ex2_a(float x){ float r; asm("ex2.approx.f32 %0,%1;" : "=f"(r) : "f"(x)); return r; }

__device__ __forceinline__ float gelu_fast(float x){
    float x2 = x * x;
    float t  = x * fmaf(x2, 0.1029413588f, 2.3021182052f);
    float z  = ex2_a(t);
    return x * z * rcp_a(z + 1.0f);
}

// ======================== fused prep ========================
__global__ void prep_all(const float* __restrict__ qkv_w, const float* __restrict__ out_w,
                         const float* __restrict__ mlp_w1, const float* __restrict__ mlp_w2,
                         const float* __restrict__ qkv_b, const float* __restrict__ enc,
                         __half* __restrict__ wqv, __half* __restrict__ wo,
                         __half* __restrict__ w1,  __half* __restrict__ w2,
                         float* __restrict__ qvb,  __half* __restrict__ eh){
    const int id = blockIdx.x;
    const int tx = threadIdx.x, ty = threadIdx.y;
    if (id >= 12288){
        int i = (id - 12288) * 256 + ty*32 + tx;
        qvb[i] = (i < Cc) ? qkv_b[i] : qkv_b[i + Cc];
        return;
    }
    if (id >= 11264){
        int i = ((id - 11264) * 256 + ty*32 + tx) * 8;
        float4 a = *(const float4*)(enc + i);
        float4 c = *(const float4*)(enc + i + 4);
        __half2 h0 = __floats2half2_rn(a.x, a.y);
        __half2 h1 = __floats2half2_rn(a.z, a.w);
        __half2 h2 = __floats2half2_rn(c.x, c.y);
        __half2 h3 = __floats2half2_rn(c.z, c.w);
        *(uint4*)(eh + i) = make_uint4(*(uint32_t*)&h0, *(uint32_t*)&h1,
                                       *(uint32_t*)&h2, *(uint32_t*)&h3);
        return;
    }
    const float* W; __half* Wt; int ldw, K, ntn, base;
    if      (id < 1024){ W = qkv_w;          Wt = wqv;         ldw = 3*Cc; K = Cc;   ntn = 32;  base = id; }
    else if (id < 2048){ W = qkv_w + 2*Cc;   Wt = wqv + Cc*Cc; ldw = 3*Cc; K = Cc;   ntn = 32;  base = id - 1024; }
    else if (id < 3072){ W = out_w;          Wt = wo;          ldw = Cc;   K = Cc;   ntn = 32;  base = id - 2048; }
    else if (id < 7168){ W = mlp_w1;         Wt = w1;          ldw = 4*Cc; K = Cc;   ntn = 128; base = id - 3072; }
    else               { W = mlp_w2;         Wt = w2;          ldw = Cc;   K = 4*Cc; ntn = 32;  base = id - 7168; }
    const int n0 = (base % ntn) * 32, k0 = (base / ntn) * 32;
    __shared__ float t[32][33];
    #pragma unroll
    for (int i = 0; i < 4; i++)
        t[ty + i*8][tx] = W[(size_t)(k0 + ty + i*8) * ldw + n0 + tx];
    __syncthreads();
    #pragma unroll
    for (int i = 0; i < 4; i++)
        Wt[(size_t)(n0 + ty + i*8) * K + k0 + tx] = __float2half_rn(t[tx][ty + i*8]);
}

// ======================== block reduce / LayerNorm ========================
__device__ __forceinline__ float block_sum(float v, volatile float* red){
    #pragma unroll
    for (int o = 16; o; o >>= 1) v += __shfl_xor_sync(0xffffffffu, v, o);
    int lane = threadIdx.x & 31, w = threadIdx.x >> 5;
    if (lane == 0) red[w] = v;
    __syncthreads();
    if (w == 0){
        v = (lane < 8) ? red[lane] : 0.f;
        #pragma unroll
        for (int o = 4; o; o >>= 1) v += __shfl_xor_sync(0xffffffffu, v, o);
    }
    return v;
}

__global__ void ln_kernel(const float* __restrict__ x, const float* __restrict__ g,
                          const float* __restrict__ b, __half* __restrict__ out){
    __shared__ float red[8];
    __shared__ float s_mu, s_rs;
    int row = blockIdx.x, tid = threadIdx.x;
    const float4 v = ((const float4*)(x + (size_t)row * Cc))[tid];
    float s = v.x + v.y + v.z + v.w;
    s = block_sum(s, red);
    if (tid == 0) s_mu = s * (1.0f / Cc);
    __syncthreads();
    float mu = s_mu;
    float dx = v.x - mu, dy = v.y - mu, dz = v.z - mu, dw = v.w - mu;
    float sq = dx*dx + dy*dy + dz*dz + dw*dw;
    sq = block_sum(sq, red);
    if (tid == 0) s_rs = rsqrtf(sq * (1.0f / Cc) + 1e-5f);
    __syncthreads();
    float rs = s_rs;
    float4 gg = ((const float4*)g)[tid], bb = ((const float4*)b)[tid];
    __half2 h0 = __floats2half2_rn(dx * rs * gg.x + bb.x, dy * rs * gg.y + bb.y);
    __half2 h1 = __floats2half2_rn(dz * rs * gg.z + bb.z, dw * rs * gg.w + bb.w);
    __half2* op = (__half2*)(out + (size_t)row * Cc);
    op[tid*2]     = h0;
    op[tid*2 + 1] = h1;
}

// ======================== fp16 GEMM (BK=32, 4-stage cp.async) ========================
#define HSTR 40
#define NSTG 4
#define STG_H (128*HSTR)
#define GH_SMEM (NSTG * STG_H * 2 * 2)

template<bool OUT_HALF>
__global__ __launch_bounds__(256) void gemm_h(
        const __half* __restrict__ A,
        const __half* __restrict__ Bt,
        const float* __restrict__ bias,
        const float* __restrict__ resid,
        void* __restrict__ outv,
        int N, int K, int do_gelu){
    extern __shared__ __half smh[];
    __half* As = smh;
    __half* Bs = smh + NSTG * STG_H;
    const int tid = threadIdx.x;
    const int lane = tid & 31, w = tid >> 5;
    const int warpM = (w & 1) * 64, warpN = (w >> 1) * 32;
    const int row0 = blockIdx.y * 128, col0 = blockIdx.x * 128;

    const int sr = tid >> 1;
    const int kh = (tid & 1) * 16;
    const __half* Ap = A + (size_t)(row0 + sr) * K + kh;
    const __half* Bp = Bt + (size_t)(col0 + sr) * K + kh;
    const uint32_t adst = (uint32_t)__cvta_generic_to_shared(&As[sr*HSTR + kh]);
    const uint32_t bdst = (uint32_t)__cvta_generic_to_shared(&Bs[sr*HSTR + kh]);

    auto load_chunk = [&](int c, int s){
        uint32_t ao = adst + s * STG_H * 2;
        uint32_t bo = bdst + s * STG_H * 2;
        const __half* ag = Ap + c * 32;
        const __half* bg = Bp + c * 32;
        CPA16(ao, ag); CPA16(ao + 16, ag + 8);
        CPA16(bo, bg); CPA16(bo + 16, bg + 8);
        asm volatile("cp.async.commit_group;" ::: "memory");
    };

    float acc[4][4][4] = {};

    const int a_row = lane & 15;
    const int a_col = (lane >> 4) * 8;
    const int b_row = (lane & 7) + ((lane >> 4) << 3);
    const int b_col = ((lane >> 3) & 1) * 8;

    auto compute = [&](int s){
        const __half* Ab = As + s * STG_H;
        const __half* Bb2 = Bs + s * STG_H;
        #pragma unroll
        for (int kk = 0; kk < 2; kk++){
            uint32_t afr[4][4];
            #pragma unroll
            for (int mt = 0; mt < 4; mt++){
                uint32_t addr = (uint32_t)__cvta_generic_to_shared(
                    &Ab[(warpM + mt*16 + a_row) * HSTR + kk*16 + a_col]);
                asm volatile("ldmatrix.sync.aligned.m8n8.x4.shared.b16 {%0,%1,%2,%3}, [%4];"
                    : "=r"(afr[mt][0]), "=r"(afr[mt][1]), "=r"(afr[mt][2]), "=r"(afr[mt][3])
                    : "r"(addr));
            }
            uint32_t bfr[2][4];
            #pragma unroll
            for (int ng = 0; ng < 2; ng++){
                uint32_t addr = (uint32_t)__cvta_generic_to_shared(
                    &Bb2[(warpN + ng*16 + b_row) * HSTR + kk*16 + b_col]);
                asm volatile("ldmatrix.sync.aligned.m8n8.x4.shared.b16 {%0,%1,%2,%3}, [%4];"
                    : "=r"(bfr[ng][0]), "=r"(bfr[ng][1]), "=r"(bfr[ng][2]), "=r"(bfr[ng][3])
                    : "r"(addr));
            }
            #pragma unroll
            for (int mt = 0; mt < 4; mt++)
                #pragma unroll
                for (int nt = 0; nt < 4; nt++){
                    uint32_t b0 = bfr[nt >> 1][(nt & 1) * 2];
                    uint32_t b1 = bfr[nt >> 1][(nt & 1) * 2 + 1];
                    asm volatile(
                        "mma.sync.aligned.m16n8k16.row.col.f32.f16.f16.f32 "
                        "{%0,%1,%2,%3},{%4,%5,%6,%7},{%8,%9},{%0,%1,%2,%3};"
                        : "+f"(acc[mt][nt][0]), "+f"(acc[mt][nt][1]),
                          "+f"(acc[mt][nt][2]), "+f"(acc[mt][nt][3])
                        : "r"(afr[mt][0]), "r"(afr[mt][1]), "r"(afr[mt][2]), "r"(afr[mt][3]),
                          "r"(b0), "r"(b1));
                }
        }
    };

    const int ntiles = K / 32;
    load_chunk(0, 0); load_chunk(1, 1); load_chunk(2, 2);
    for (int t = 0; t < ntiles; t++){
        asm volatile("cp.async.wait_group 2;" ::: "memory");
        __syncthreads();
        if (t + 3 < ntiles) load_chunk(t + 3, (t + 3) & 3);
        compute(t & 3);
    }

    #pragma unroll
    for (int mt = 0; mt < 4; mt++){
        #pragma unroll
        for (int nt = 0; nt < 4; nt++){
            int rr = row0 + warpM + mt*16 + (lane >> 2);
            int cc = col0 + warpN + nt*8 + (lane & 3) * 2;
            #pragma unroll
            for (int half = 0; half < 2; half++){
                int r = rr + half * 8;
                float v0 = acc[mt][nt][half*2]     + bias[cc];
                float v1 = acc[mt][nt][half*2 + 1] + bias[cc + 1];
                if (resid){
                    const float2 rv = *(const float2*)&resid[(size_t)r * N + cc];
                    v0 += rv.x; v1 += rv.y;
                }
                if (do_gelu){
                    v0 = gelu_fast(v0);
                    v1 = gelu_fast(v1);
                }
                if (OUT_HALF){
                    *(__half2*)&((__half*)outv)[(size_t)r * N + cc] = __floats2half2_rn(v0, v1);
                } else {
                    *(float2*)&((float*)outv)[(size_t)r * N + cc] = make_float2(v0, v1);
                }
            }
        }
    }
}

// ======================== Attention: packed fp16 exp + ones-column row sums ========================
#define HQ 72
#define QVLD (2*Cc)
#define ATTN_SMEM (((128 + 128 + 128) * HQ * 2) + 128)   // +128 pad for ng=4 ldmatrix over-read

__device__ __forceinline__ float lif_s2(float I){
    float u  = rcp_a(I);
    float wv = 1.0f - u;
    float lg = lg2_a(wv);
    float dd = fmaf(lg, -0.0138629436112f, 0.002f);
    float s2 = rcp_a(dd) * 0.180336879f;
    return (I > 1.0000001f) ? s2 : 0.0f;
}

__global__ __launch_bounds__(256) void attn_tc(
        const __half* __restrict__ Q, const __half* __restrict__ V,
        const __half* __restrict__ EH, const float* __restrict__ gain,
        const float* __restrict__ bias, __half* __restrict__ out){
    extern __shared__ __half smh[];
    __half* PsH = smh;
    __half* EsH = smh + 128*HQ;
    __half* VsH = smh + (128 + 128)*HQ;

    const int tid = threadIdx.x;
    const int lane = tid & 31, w = tid >> 5;
    const int bh = blockIdx.y, b = bh >> 4, h = bh & 15;
    const int t0 = (gridDim.x - 1 - blockIdx.x) << 7;
    const int rowbase = w << 4;

    const int a_row = lane & 15;
    const int a_col = (lane >> 4) * 8;
    const int b_row = (lane & 7) + ((lane >> 4) << 3);
    const int b_col = ((lane >> 3) & 1) * 8;
    const int v_row = (lane & 7) + ((lane >> 3) & 1) * 8;
    const int v_col = (lane >> 4) * 8;

    // ---- stage Q tile
    {
        const int qr = tid >> 1, qc = (tid & 1) * 32;
        const __half* qp = Q + ((size_t)(b*Tt + t0 + qr)) * QVLD + h*Dd + qc;
        #pragma unroll
        for (int j = 0; j < 4; j++)
            *(uint4*)&PsH[qr*HQ + qc + j*8] = *(const uint4*)(qp + j*8);
    }
    // ---- one-time init of V ones-column (cols 64..71; cp.async only writes 0..63)
    if (tid < 128){
        *(uint4*)&VsH[tid*HQ + 64] = make_uint4(0x00003C00u, 0u, 0u, 0u);  // {1.0h, 0...}
    }
    __syncthreads();

    uint32_t qa[4][4];
    #pragma unroll
    for (int kk = 0; kk < 4; kk++){
        uint32_t addr = (uint32_t)__cvta_generic_to_shared(
            &PsH[(rowbase + a_row) * HQ + kk*16 + a_col]);
        asm volatile("ldmatrix.sync.aligned.m8n8.x4.shared.b16 {%0,%1,%2,%3}, [%4];"
            : "=r"(qa[kk][0]), "=r"(qa[kk][1]), "=r"(qa[kk][2]), "=r"(qa[kk][3])
            : "r"(addr));
    }

    const int r = lane >> 2;
    const int cq = (lane & 3) << 1;
    const int tA = t0 + rowbase + r;
    const int tB = tA + 8;
    const float gA = gain[h*Tt + tA], bA = bias[h*Tt + tA];
    const float gB = gain[h*Tt + tB], bB = bias[h*Tt + tB];
    const int twmax = t0 + rowbase + 15;
    const int wmin  = t0 + rowbase;

    float oacc[8][4] = {};
    float oaccS[4] = {};            // col 64 (row sums) + junk cols
    float mA = 0.f, mB = 0.f;

    const int s_lr = tid >> 2;
    const int s_ck = (tid & 3) * 16;
    auto stage_tile = [&](int s0, int sbuf){
        const __half* eg = EH + ((size_t)(h*Tt + s0 + s_lr)) * Dd + s_ck;
        uint32_t ed = (uint32_t)__cvta_generic_to_shared(&EsH[sbuf*64*HQ + s_lr*HQ + s_ck]);
        CPA16(ed, eg); CPA16(ed + 16, eg + 8);
        const __half* vg = V + ((size_t)(b*Tt + s0 + s_lr)) * QVLD + h*Dd + s_ck;
        uint32_t vd = (uint32_t)__cvta_generic_to_shared(&VsH[sbuf*64*HQ + s_lr*HQ + s_ck]);
        CPA16(vd, vg); CPA16(vd + 16, vg + 8);
        asm volatile("cp.async.commit_group;" ::: "memory");
    };

    const int nIt = (t0 >> 6) + 2;
    stage_tile(0, 0);
    int buf = 0;

    for (int it = 0; it < nIt; it++){
        const int s0 = it << 6;
        asm volatile("cp.async.wait_group 0;" ::: "memory");
        __syncthreads();
        if (it + 1 < nIt) stage_tile(s0 + 64, buf ^ 1);

        if (s0 <= twmax){
            const __half* Eb = EsH + buf*64*HQ;
            const __half* Vb = VsH + buf*64*HQ;

            // ---- MMA1: S = Q . E^T
            float sacc[8][4] = {};
            #pragma unroll
            for (int kk = 0; kk < 4; kk++){
                uint32_t bfr[4][4];
                #pragma unroll
                for (int ng = 0; ng < 4; ng++){
                    uint32_t addr = (uint32_t)__cvta_generic_to_shared(
                        &Eb[(ng*16 + b_row) * HQ + kk*16 + b_col]);
                    asm volatile("ldmatrix.sync.aligned.m8n8.x4.shared.b16 {%0,%1,%2,%3}, [%4];"
                        : "=r"(bfr[ng][0]), "=r"(bfr[ng][1]), "=r"(bfr[ng][2]), "=r"(bfr[ng][3])
                        : "r"(addr));
                }
                #pragma unroll
                for (int nt = 0; nt < 8; nt++){
                    uint32_t b0 = bfr[nt >> 1][(nt & 1) * 2];
                    uint32_t b1 = bfr[nt >> 1][(nt & 1) * 2 + 1];
                    asm volatile(
                        "mma.sync.aligned.m16n8k16.row.col.f32.f16.f16.f32 "
                        "{%0,%1,%2,%3},{%4,%5,%6,%7},{%8,%9},{%0,%1,%2,%3};"
                        : "+f"(sacc[nt][0]), "+f"(sacc[nt][1]),
                          "+f"(sacc[nt][2]), "+f"(sacc[nt][3])
                        : "r"(qa[kk][0]), "r"(qa[kk][1]), "r"(qa[kk][2]), "r"(qa[kk][3]),
                          "r"(b0), "r"(b1));
                }
            }

            // ---- LIF (log2) + causal
            float tmaxA = 0.f, tmaxB = 0.f;
            if (s0 + 63 <= wmin){
                #pragma unroll
                for (int nt = 0; nt < 8; nt++){
                    float v00 = lif_s2(fmaf(gA, sacc[nt][0], bA));
                    float v01 = lif_s2(fmaf(gA, sacc[nt][1], bA));
                    float v10 = lif_s2(fmaf(gB, sacc[nt][2], bB));
                    float v11 = lif_s2(fmaf(gB, sacc[nt][3], bB));
                    sacc[nt][0] = v00; sacc[nt][1] = v01; sacc[nt][2] = v10; sacc[nt][3] = v11;
                    tmaxA = fmaxf(tmaxA, fmaxf(v00, v01));
                    tmaxB = fmaxf(tmaxB, fmaxf(v10, v11));
                }
            } else {
                #pragma unroll
                for (int nt = 0; nt < 8; nt++){
                    int sb = s0 + nt*8 + cq;
                    float v00 = (sb     <= tA) ? lif_s2(fmaf(gA, sacc[nt][0], bA)) : -1e30f;
                    float v01 = (sb + 1 <= tA) ? lif_s2(fmaf(gA, sacc[nt][1], bA)) : -1e30f;
                    float v10 = (sb     <= tB) ? lif_s2(fmaf(gB, sacc[nt][2], bB)) : -1e30f;
                    float v11 = (sb + 1 <= tB) ? lif_s2(fmaf(gB, sacc[nt][3], bB)) : -1e30f;
                    sacc[nt][0] = v00; sacc[nt][1] = v01; sacc[nt][2] = v10; sacc[nt][3] = v11;
                    tmaxA = fmaxf(tmaxA, fmaxf(v00, v01));
                    tmaxB = fmaxf(tmaxB, fmaxf(v10, v11));
                }
            }
            tmaxA = fmaxf(tmaxA, __shfl_xor_sync(0xffffffffu, tmaxA, 1));
            tmaxA = fmaxf(tmaxA, __shfl_xor_sync(0xffffffffu, tmaxA, 2));
            tmaxB = fmaxf(tmaxB, __shfl_xor_sync(0xffffffffu, tmaxB, 1));
            tmaxB = fmaxf(tmaxB, __shfl_xor_sync(0xffffffffu, tmaxB, 2));

            if (__any_sync(0xffffffffu, (tmaxA > mA) || (tmaxB > mB))){
                float mAn = fmaxf(mA, tmaxA), mBn = fmaxf(mB, tmaxB);
                float scA = ex2_a(mA - mAn), scB = ex2_a(mB - mBn);
                mA = mAn; mB = mBn;
                #pragma unroll
                for (int nt = 0; nt < 8; nt++){
                    oacc[nt][0] *= scA; oacc[nt][1] *= scA;
                    oacc[nt][2] *= scB; oacc[nt][3] *= scB;
                }
                oaccS[0] *= scA; oaccS[1] *= scA;
                oaccS[2] *= scB; oaccS[3] *= scB;
            }

            // ---- packed fp16 exp -> P fragments (no separate psum bookkeeping)
            uint32_t pa[4][4];
            #pragma unroll
            for (int nt = 0; nt < 8; nt++){
                __half2 hA = __floats2half2_rn(sacc[nt][0] - mA, sacc[nt][1] - mA);
                __half2 hB = __floats2half2_rn(sacc[nt][2] - mB, sacc[nt][3] - mB);
                uint32_t pA, pB;
                asm("ex2.approx.f16x2 %0, %1;" : "=r"(pA) : "r"(*(uint32_t*)&hA));
                asm("ex2.approx.f16x2 %0, %1;" : "=r"(pB) : "r"(*(uint32_t*)&hB));
                pa[nt >> 1][(nt & 1) * 2    ] = pA;
                pa[nt >> 1][(nt & 1) * 2 + 1] = pB;
            }

            // ---- MMA2: O += P.V  (+ ones-column gives row sums in col 64)
            #pragma unroll
            for (int kk = 0; kk < 4; kk++){
                uint32_t bfr[5][4];
                #pragma unroll
                for (int ng = 0; ng < 5; ng++){
                    uint32_t addr = (uint32_t)__cvta_generic_to_shared(
                        &Vb[(kk*16 + v_row) * HQ + ng*16 + v_col]);
                    asm volatile("ldmatrix.sync.aligned.m8n8.x4.trans.shared.b16 {%0,%1,%2,%3}, [%4];"
                        : "=r"(bfr[ng][0]), "=r"(bfr[ng][1]), "=r"(bfr[ng][2]), "=r"(bfr[ng][3])
                        : "r"(addr));
                }
                #pragma unroll
                for (int nt = 0; nt < 8; nt++){
                    uint32_t b0 = bfr[nt >> 1][(nt & 1) * 2];
                    uint32_t b1 = bfr[nt >> 1][(nt & 1) * 2 + 1];
                    asm volatile(
                        "mma.sync.aligned.m16n8k16.row.col.f32.f16.f16.f32 "
                        "{%0,%1,%2,%3},{%4,%5,%6,%7},{%8,%9},{%0,%1,%2,%3};"
                        : "+f"(oacc[nt][0]), "+f"(oacc[nt][1]),
                          "+f"(oacc[nt][2]), "+f"(oacc[nt][3])
                        : "r"(pa[kk][0]), "r"(pa[kk][1]), "r"(pa[kk][2]), "r"(pa[kk][3]),
                          "r"(b0), "r"(b1));
                }
                asm volatile(
                    "mma.sync.aligned.m16n8k16.row.col.f32.f16.f16.f32 "
                    "{%0,%1,%2,%3},{%4,%5,%6,%7},{%8,%9},{%0,%1,%2,%3};"
                    : "+f"(oaccS[0]), "+f"(oaccS[1]), "+f"(oaccS[2]), "+f"(oaccS[3])
                    : "r"(pa[kk][0]), "r"(pa[kk][1]), "r"(pa[kk][2]), "r"(pa[kk][3]),
                      "r"(bfr[4][0]), "r"(bfr[4][1]));
            }
        }
        buf ^= 1;
    }

    // row sums live in col 64 (quad lane 0's c0 / c2); broadcast within quad
    float psumA = __shfl_sync(0xffffffffu, oaccS[0], lane & 28);
    float psumB = __shfl_sync(0xffffffffu, oaccS[2], lane & 28);
    float invA = 1.0f / psumA;
    float invB = 1.0f / psumB;

    __half* opA = out + ((size_t)(b*Tt + tA)) * Cc + h*Dd;
    __half* opB = out + ((size_t)(b*Tt + tB)) * Cc + h*Dd;
    #pragma unroll
    for (int nt = 0; nt < 8; nt++){
        int d = nt*8 + cq;
        *(__half2*)&opA[d] = __floats2half2_rn(oacc[nt][0]*invA, oacc[nt][1]*invA);
        *(__half2*)&opB[d] = __floats2half2_rn(oacc[nt][2]*invB, oacc[nt][3]*invB);
    }
}

// ======================== launch ========================
extern "C" void kernel_launch(void* const* d_in, const int* in_sizes, int n_in,
                              void* d_out, int out_size){
    const float* x      = (const float*)d_in[0];
    const float* ln1_g  = (const float*)d_in[1];
    const float* ln1_b  = (const float*)d_in[2];
    const float* qkv_w  = (const float*)d_in[3];
    const float* qkv_b  = (const float*)d_in[4];
    const float* out_w  = (const float*)d_in[5];
    const float* out_b  = (const float*)d_in[6];
    const float* ln2_g  = (const float*)d_in[7];
    const float* ln2_b  = (const float*)d_in[8];
    const float* mlp_w1 = (const float*)d_in[9];
    const float* mlp_b1 = (const float*)d_in[10];
    const float* mlp_w2 = (const float*)d_in[11];
    const float* mlp_b2 = (const float*)d_in[12];
    const float* enc    = (const float*)d_in[13];
    const float* gain   = (const float*)d_in[14];
    const float* battn  = (const float*)d_in[15];
    float* outp = (float*)d_out;

    __half *xn, *qv, *att, *hbuf, *wqv, *wo, *w1, *w2, *eh;
    float *x1, *qvb;
    cudaGetSymbolAddress((void**)&xn,   g_xn);
    cudaGetSymbolAddress((void**)&qv,   g_qv);
    cudaGetSymbolAddress((void**)&att,  g_att);
    cudaGetSymbolAddress((void**)&x1,   g_x1);
    cudaGetSymbolAddress((void**)&hbuf, g_h);
    cudaGetSymbolAddress((void**)&wqv,  g_wqv);
    cudaGetSymbolAddress((void**)&wo,   g_wo);
    cudaGetSymbolAddress((void**)&w1,   g_w1);
    cudaGetSymbolAddress((void**)&w2,   g_w2);
    cudaGetSymbolAddress((void**)&qvb,  g_qvb);
    cudaGetSymbolAddress((void**)&eh,   g_eh);

    cudaFuncSetAttribute(attn_tc,       cudaFuncAttributeMaxDynamicSharedMemorySize, ATTN_SMEM);
    cudaFuncSetAttribute(gemm_h<true>,  cudaFuncAttributeMaxDynamicSharedMemorySize, GH_SMEM);
    cudaFuncSetAttribute(gemm_h<false>, cudaFuncAttributeMaxDynamicSharedMemorySize, GH_SMEM);

    const int M = Bb * Tt;

    prep_all<<<12296, dim3(32,8)>>>(qkv_w, out_w, mlp_w1, mlp_w2, qkv_b, enc,
                                    wqv, wo, w1, w2, qvb, eh);

    ln_kernel<<<M, 256>>>(x, ln1_g, ln1_b, xn);
    gemm_h<true ><<<dim3(2*Cc/128, M/128), 256, GH_SMEM>>>(xn, wqv, qvb, nullptr, qv, 2*Cc, Cc, 0);
    attn_tc<<<dim3(Tt/128, Bb*Hh), 256, ATTN_SMEM>>>(qv, qv + Cc, eh, gain, battn, att);
    gemm_h<false><<<dim3(Cc/128, M/128), 256, GH_SMEM>>>(att, wo, out_b, x, x1, Cc, Cc, 0);
    ln_kernel<<<M, 256>>>(x1, ln2_g, ln2_b, xn);
    gemm_h<true ><<<dim3(4*Cc/128, M/128), 256, GH_SMEM>>>(xn, w1, mlp_b1, nullptr, hbuf, 4*Cc, Cc, 1);
    gemm_h<false><<<dim3(Cc/128, M/128), 256, GH_SMEM>>>(hbuf, w2, mlp_b2, x1, outp, Cc, 4*Cc, 0);
}

// round 17
// speedup vs baseline: 1.0800x; 1.0067x over previous
#include <cuda_runtime.h>
#include <cuda_fp16.h>
#include <math.h>
#include <stdint.h>

#define Bb 2
#define Tt 2048
#define Cc 1024
#define Hh 16
#define Dd 64

__device__ __half g_xn [Bb*Tt*Cc];
__device__ __half g_qv [Bb*Tt*2*Cc];
__device__ __half g_att[Bb*Tt*Cc];
__device__ float  g_x1 [Bb*Tt*Cc];
__device__ __half g_h  [Bb*Tt*4*Cc];
__device__ __half g_wqv[2*Cc*Cc];
__device__ __half g_wo [Cc*Cc];
__device__ __half g_w1 [4*Cc*Cc];
__device__ __half g_w2 [Cc*4*Cc];
__device__ float  g_qvb[2*Cc];
__device__ __half g_eh [Hh*Tt*Dd];

#define CPA16(dst, src) \
    asm volatile("cp.async.cg.shared.global [%0], [%1], 16;" :: "r"(dst), "l"(src) : "memory")

__device__ __forceinline__ float rcp_a(float x){ float r; asm("rcp.approx.f32 %0,%1;" : "=f"(r) : "f"(x)); return r; }
__device__ __forceinline__ float lg2_a(float x){ float r; asm("lg2.approx.f32 %0,%1;" : "=f"(r) : "f"(x)); return r; }
__device__ __forceinline__ float ex2_a(float x){ float r; asm("ex2.approx.f32 %0,%1;" : "=f"(r) : "f"(x)); return r; }

__device__ __forceinline__ float gelu_fast(float x){
    float x2 = x * x;
    float t  = x * fmaf(x2, 0.1029413588f, 2.3021182052f);
    float z  = ex2_a(t);
    return x * z * rcp_a(z + 1.0f);
}

// ======================== fused prep ========================
__global__ void prep_all(const float* __restrict__ qkv_w, const float* __restrict__ out_w,
                         const float* __restrict__ mlp_w1, const float* __restrict__ mlp_w2,
                         const float* __restrict__ qkv_b, const float* __restrict__ enc,
                         __half* __restrict__ wqv, __half* __restrict__ wo,
                         __half* __restrict__ w1,  __half* __restrict__ w2,
                         float* __restrict__ qvb,  __half* __restrict__ eh){
    const int id = blockIdx.x;
    const int tx = threadIdx.x, ty = threadIdx.y;
    if (id >= 12288){
        int i = (id - 12288) * 256 + ty*32 + tx;
        qvb[i] = (i < Cc) ? qkv_b[i] : qkv_b[i + Cc];
        return;
    }
    if (id >= 11264){
        int i = ((id - 11264) * 256 + ty*32 + tx) * 8;
        float4 a = *(const float4*)(enc + i);
        float4 c = *(const float4*)(enc + i + 4);
        __half2 h0 = __floats2half2_rn(a.x, a.y);
        __half2 h1 = __floats2half2_rn(a.z, a.w);
        __half2 h2 = __floats2half2_rn(c.x, c.y);
        __half2 h3 = __floats2half2_rn(c.z, c.w);
        *(uint4*)(eh + i) = make_uint4(*(uint32_t*)&h0, *(uint32_t*)&h1,
                                       *(uint32_t*)&h2, *(uint32_t*)&h3);
        return;
    }
    const float* W; __half* Wt; int ldw, K, ntn, base;
    if      (id < 1024){ W = qkv_w;          Wt = wqv;         ldw = 3*Cc; K = Cc;   ntn = 32;  base = id; }
    else if (id < 2048){ W = qkv_w + 2*Cc;   Wt = wqv + Cc*Cc; ldw = 3*Cc; K = Cc;   ntn = 32;  base = id - 1024; }
    else if (id < 3072){ W = out_w;          Wt = wo;          ldw = Cc;   K = Cc;   ntn = 32;  base = id - 2048; }
    else if (id < 7168){ W = mlp_w1;         Wt = w1;          ldw = 4*Cc; K = Cc;   ntn = 128; base = id - 3072; }
    else               { W = mlp_w2;         Wt = w2;          ldw = Cc;   K = 4*Cc; ntn = 32;  base = id - 7168; }
    const int n0 = (base % ntn) * 32, k0 = (base / ntn) * 32;
    __shared__ float t[32][33];
    #pragma unroll
    for (int i = 0; i < 4; i++)
        t[ty + i*8][tx] = W[(size_t)(k0 + ty + i*8) * ldw + n0 + tx];
    __syncthreads();
    #pragma unroll
    for (int i = 0; i < 4; i++)
        Wt[(size_t)(n0 + ty + i*8) * K + k0 + tx] = __float2half_rn(t[tx][ty + i*8]);
}

// ======================== block reduce / LayerNorm ========================
__device__ __forceinline__ float block_sum(float v, volatile float* red){
    #pragma unroll
    for (int o = 16; o; o >>= 1) v += __shfl_xor_sync(0xffffffffu, v, o);
    int lane = threadIdx.x & 31, w = threadIdx.x >> 5;
    if (lane == 0) red[w] = v;
    __syncthreads();
    if (w == 0){
        v = (lane < 8) ? red[lane] : 0.f;
        #pragma unroll
        for (int o = 4; o; o >>= 1) v += __shfl_xor_sync(0xffffffffu, v, o);
    }
    return v;
}

__global__ void ln_kernel(const float* __restrict__ x, const float* __restrict__ g,
                          const float* __restrict__ b, __half* __restrict__ out){
    __shared__ float red[8];
    __shared__ float s_mu, s_rs;
    int row = blockIdx.x, tid = threadIdx.x;
    const float4 v = ((const float4*)(x + (size_t)row * Cc))[tid];
    float s = v.x + v.y + v.z + v.w;
    s = block_sum(s, red);
    if (tid == 0) s_mu = s * (1.0f / Cc);
    __syncthreads();
    float mu = s_mu;
    float dx = v.x - mu, dy = v.y - mu, dz = v.z - mu, dw = v.w - mu;
    float sq = dx*dx + dy*dy + dz*dz + dw*dw;
    sq = block_sum(sq, red);
    if (tid == 0) s_rs = rsqrtf(sq * (1.0f / Cc) + 1e-5f);
    __syncthreads();
    float rs = s_rs;
    float4 gg = ((const float4*)g)[tid], bb = ((const float4*)b)[tid];
    __half2 h0 = __floats2half2_rn(dx * rs * gg.x + bb.x, dy * rs * gg.y + bb.y);
    __half2 h1 = __floats2half2_rn(dz * rs * gg.z + bb.z, dw * rs * gg.w + bb.w);
    __half2* op = (__half2*)(out + (size_t)row * Cc);
    op[tid*2]     = h0;
    op[tid*2 + 1] = h1;
}

// ======================== fp16 GEMM (BK=32, 4-stage cp.async) ========================
#define HSTR 40
#define NSTG 4
#define STG_H (128*HSTR)
#define GH_SMEM (NSTG * STG_H * 2 * 2)

template<bool OUT_HALF>
__global__ __launch_bounds__(256) void gemm_h(
        const __half* __restrict__ A,
        const __half* __restrict__ Bt,
        const float* __restrict__ bias,
        const float* __restrict__ resid,
        void* __restrict__ outv,
        int N, int K, int do_gelu){
    extern __shared__ __half smh[];
    __half* As = smh;
    __half* Bs = smh + NSTG * STG_H;
    const int tid = threadIdx.x;
    const int lane = tid & 31, w = tid >> 5;
    const int warpM = (w & 1) * 64, warpN = (w >> 1) * 32;
    const int row0 = blockIdx.y * 128, col0 = blockIdx.x * 128;

    const int sr = tid >> 1;
    const int kh = (tid & 1) * 16;
    const __half* Ap = A + (size_t)(row0 + sr) * K + kh;
    const __half* Bp = Bt + (size_t)(col0 + sr) * K + kh;
    const uint32_t adst = (uint32_t)__cvta_generic_to_shared(&As[sr*HSTR + kh]);
    const uint32_t bdst = (uint32_t)__cvta_generic_to_shared(&Bs[sr*HSTR + kh]);

    auto load_chunk = [&](int c, int s){
        uint32_t ao = adst + s * STG_H * 2;
        uint32_t bo = bdst + s * STG_H * 2;
        const __half* ag = Ap + c * 32;
        const __half* bg = Bp + c * 32;
        CPA16(ao, ag); CPA16(ao + 16, ag + 8);
        CPA16(bo, bg); CPA16(bo + 16, bg + 8);
        asm volatile("cp.async.commit_group;" ::: "memory");
    };

    float acc[4][4][4] = {};

    const int a_row = lane & 15;
    const int a_col = (lane >> 4) * 8;
    const int b_row = (lane & 7) + ((lane >> 4) << 3);
    const int b_col = ((lane >> 3) & 1) * 8;

    auto compute = [&](int s){
        const __half* Ab = As + s * STG_H;
        const __half* Bb2 = Bs + s * STG_H;
        #pragma unroll
        for (int kk = 0; kk < 2; kk++){
            uint32_t afr[4][4];
            #pragma unroll
            for (int mt = 0; mt < 4; mt++){
                uint32_t addr = (uint32_t)__cvta_generic_to_shared(
                    &Ab[(warpM + mt*16 + a_row) * HSTR + kk*16 + a_col]);
                asm volatile("ldmatrix.sync.aligned.m8n8.x4.shared.b16 {%0,%1,%2,%3}, [%4];"
                    : "=r"(afr[mt][0]), "=r"(afr[mt][1]), "=r"(afr[mt][2]), "=r"(afr[mt][3])
                    : "r"(addr));
            }
            uint32_t bfr[2][4];
            #pragma unroll
            for (int ng = 0; ng < 2; ng++){
                uint32_t addr = (uint32_t)__cvta_generic_to_shared(
                    &Bb2[(warpN + ng*16 + b_row) * HSTR + kk*16 + b_col]);
                asm volatile("ldmatrix.sync.aligned.m8n8.x4.shared.b16 {%0,%1,%2,%3}, [%4];"
                    : "=r"(bfr[ng][0]), "=r"(bfr[ng][1]), "=r"(bfr[ng][2]), "=r"(bfr[ng][3])
                    : "r"(addr));
            }
            #pragma unroll
            for (int mt = 0; mt < 4; mt++)
                #pragma unroll
                for (int nt = 0; nt < 4; nt++){
                    uint32_t b0 = bfr[nt >> 1][(nt & 1) * 2];
                    uint32_t b1 = bfr[nt >> 1][(nt & 1) * 2 + 1];
                    asm volatile(
                        "mma.sync.aligned.m16n8k16.row.col.f32.f16.f16.f32 "
                        "{%0,%1,%2,%3},{%4,%5,%6,%7},{%8,%9},{%0,%1,%2,%3};"
                        : "+f"(acc[mt][nt][0]), "+f"(acc[mt][nt][1]),
                          "+f"(acc[mt][nt][2]), "+f"(acc[mt][nt][3])
                        : "r"(afr[mt][0]), "r"(afr[mt][1]), "r"(afr[mt][2]), "r"(afr[mt][3]),
                          "r"(b0), "r"(b1));
                }
        }
    };

    const int ntiles = K / 32;
    load_chunk(0, 0); load_chunk(1, 1); load_chunk(2, 2);
    for (int t = 0; t < ntiles; t++){
        asm volatile("cp.async.wait_group 2;" ::: "memory");
        __syncthreads();
        if (t + 3 < ntiles) load_chunk(t + 3, (t + 3) & 3);
        compute(t & 3);
    }

    #pragma unroll
    for (int mt = 0; mt < 4; mt++){
        #pragma unroll
        for (int nt = 0; nt < 4; nt++){
            int rr = row0 + warpM + mt*16 + (lane >> 2);
            int cc = col0 + warpN + nt*8 + (lane & 3) * 2;
            #pragma unroll
            for (int half = 0; half < 2; half++){
                int r = rr + half * 8;
                float v0 = acc[mt][nt][half*2]     + bias[cc];
                float v1 = acc[mt][nt][half*2 + 1] + bias[cc + 1];
                if (resid){
                    const float2 rv = *(const float2*)&resid[(size_t)r * N + cc];
                    v0 += rv.x; v1 += rv.y;
                }
                if (do_gelu){
                    v0 = gelu_fast(v0);
                    v1 = gelu_fast(v1);
                }
                if (OUT_HALF){
                    *(__half2*)&((__half*)outv)[(size_t)r * N + cc] = __floats2half2_rn(v0, v1);
                } else {
                    *(float2*)&((float*)outv)[(size_t)r * N + cc] = make_float2(v0, v1);
                }
            }
        }
    }
}

// ======================== Attention: packed fp16 exp + constant ones-fragment row sums ========================
#define HQ 72
#define QVLD (2*Cc)
#define ATTN_SMEM ((128 + 128 + 128) * HQ * 2)

__device__ __forceinline__ float lif_s2(float I){
    float u  = rcp_a(I);
    float wv = 1.0f - u;
    float lg = lg2_a(wv);
    float dd = fmaf(lg, -0.0138629436112f, 0.002f);
    float s2 = rcp_a(dd) * 0.180336879f;
    return (I > 1.0000001f) ? s2 : 0.0f;
}

__global__ __launch_bounds__(256) void attn_tc(
        const __half* __restrict__ Q, const __half* __restrict__ V,
        const __half* __restrict__ EH, const float* __restrict__ gain,
        const float* __restrict__ bias, __half* __restrict__ out){
    extern __shared__ __half smh[];
    __half* PsH = smh;
    __half* EsH = smh + 128*HQ;
    __half* VsH = smh + (128 + 128)*HQ;

    const int tid = threadIdx.x;
    const int lane = tid & 31, w = tid >> 5;
    const int bh = blockIdx.y, b = bh >> 4, h = bh & 15;
    const int t0 = (gridDim.x - 1 - blockIdx.x) << 7;
    const int rowbase = w << 4;

    const int a_row = lane & 15;
    const int a_col = (lane >> 4) * 8;
    const int b_row = (lane & 7) + ((lane >> 4) << 3);
    const int b_col = ((lane >> 3) & 1) * 8;
    const int v_row = (lane & 7) + ((lane >> 3) & 1) * 8;
    const int v_col = (lane >> 4) * 8;

    // constant B-fragment for the ones-column (n=0 of its n8 tile => lanes 0-3)
    const uint32_t ones_frag = (lane < 4) ? 0x3C003C00u : 0u;

    // ---- stage Q tile
    {
        const int qr = tid >> 1, qc = (tid & 1) * 32;
        const __half* qp = Q + ((size_t)(b*Tt + t0 + qr)) * QVLD + h*Dd + qc;
        #pragma unroll
        for (int j = 0; j < 4; j++)
            *(uint4*)&PsH[qr*HQ + qc + j*8] = *(const uint4*)(qp + j*8);
    }
    __syncthreads();

    uint32_t qa[4][4];
    #pragma unroll
    for (int kk = 0; kk < 4; kk++){
        uint32_t addr = (uint32_t)__cvta_generic_to_shared(
            &PsH[(rowbase + a_row) * HQ + kk*16 + a_col]);
        asm volatile("ldmatrix.sync.aligned.m8n8.x4.shared.b16 {%0,%1,%2,%3}, [%4];"
            : "=r"(qa[kk][0]), "=r"(qa[kk][1]), "=r"(qa[kk][2]), "=r"(qa[kk][3])
            : "r"(addr));
    }

    const int r = lane >> 2;
    const int cq = (lane & 3) << 1;
    const int tA = t0 + rowbase + r;
    const int tB = tA + 8;
    const float gA = gain[h*Tt + tA], bA = bias[h*Tt + tA];
    const float gB = gain[h*Tt + tB], bB = bias[h*Tt + tB];
    const int twmax = t0 + rowbase + 15;
    const int wmin  = t0 + rowbase;

    float oacc[8][4] = {};
    float oaccS[4] = {};
    float mA = 0.f, mB = 0.f;

    const int s_lr = tid >> 2;
    const int s_ck = (tid & 3) * 16;
    auto stage_tile = [&](int s0, int sbuf){
        const __half* eg = EH + ((size_t)(h*Tt + s0 + s_lr)) * Dd + s_ck;
        uint32_t ed = (uint32_t)__cvta_generic_to_shared(&EsH[sbuf*64*HQ + s_lr*HQ + s_ck]);
        CPA16(ed, eg); CPA16(ed + 16, eg + 8);
        const __half* vg = V + ((size_t)(b*Tt + s0 + s_lr)) * QVLD + h*Dd + s_ck;
        uint32_t vd = (uint32_t)__cvta_generic_to_shared(&VsH[sbuf*64*HQ + s_lr*HQ + s_ck]);
        CPA16(vd, vg); CPA16(vd + 16, vg + 8);
        asm volatile("cp.async.commit_group;" ::: "memory");
    };

    const int nIt = (t0 >> 6) + 2;
    stage_tile(0, 0);
    int buf = 0;

    for (int it = 0; it < nIt; it++){
        const int s0 = it << 6;
        asm volatile("cp.async.wait_group 0;" ::: "memory");
        __syncthreads();
        if (it + 1 < nIt) stage_tile(s0 + 64, buf ^ 1);

        if (s0 <= twmax){
            const __half* Eb = EsH + buf*64*HQ;
            const __half* Vb = VsH + buf*64*HQ;

            // ---- MMA1: S = Q . E^T
            float sacc[8][4] = {};
            #pragma unroll
            for (int kk = 0; kk < 4; kk++){
                uint32_t bfr[4][4];
                #pragma unroll
                for (int ng = 0; ng < 4; ng++){
                    uint32_t addr = (uint32_t)__cvta_generic_to_shared(
                        &Eb[(ng*16 + b_row) * HQ + kk*16 + b_col]);
                    asm volatile("ldmatrix.sync.aligned.m8n8.x4.shared.b16 {%0,%1,%2,%3}, [%4];"
                        : "=r"(bfr[ng][0]), "=r"(bfr[ng][1]), "=r"(bfr[ng][2]), "=r"(bfr[ng][3])
                        : "r"(addr));
                }
                #pragma unroll
                for (int nt = 0; nt < 8; nt++){
                    uint32_t b0 = bfr[nt >> 1][(nt & 1) * 2];
                    uint32_t b1 = bfr[nt >> 1][(nt & 1) * 2 + 1];
                    asm volatile(
                        "mma.sync.aligned.m16n8k16.row.col.f32.f16.f16.f32 "
                        "{%0,%1,%2,%3},{%4,%5,%6,%7},{%8,%9},{%0,%1,%2,%3};"
                        : "+f"(sacc[nt][0]), "+f"(sacc[nt][1]),
                          "+f"(sacc[nt][2]), "+f"(sacc[nt][3])
                        : "r"(qa[kk][0]), "r"(qa[kk][1]), "r"(qa[kk][2]), "r"(qa[kk][3]),
                          "r"(b0), "r"(b1));
                }
            }

            // ---- LIF (log2) + causal
            float tmaxA = 0.f, tmaxB = 0.f;
            if (s0 + 63 <= wmin){
                #pragma unroll
                for (int nt = 0; nt < 8; nt++){
                    float v00 = lif_s2(fmaf(gA, sacc[nt][0], bA));
                    float v01 = lif_s2(fmaf(gA, sacc[nt][1], bA));
                    float v10 = lif_s2(fmaf(gB, sacc[nt][2], bB));
                    float v11 = lif_s2(fmaf(gB, sacc[nt][3], bB));
                    sacc[nt][0] = v00; sacc[nt][1] = v01; sacc[nt][2] = v10; sacc[nt][3] = v11;
                    tmaxA = fmaxf(tmaxA, fmaxf(v00, v01));
                    tmaxB = fmaxf(tmaxB, fmaxf(v10, v11));
                }
            } else {
                #pragma unroll
                for (int nt = 0; nt < 8; nt++){
                    int sb = s0 + nt*8 + cq;
                    float v00 = (sb     <= tA) ? lif_s2(fmaf(gA, sacc[nt][0], bA)) : -1e30f;
                    float v01 = (sb + 1 <= tA) ? lif_s2(fmaf(gA, sacc[nt][1], bA)) : -1e30f;
                    float v10 = (sb     <= tB) ? lif_s2(fmaf(gB, sacc[nt][2], bB)) : -1e30f;
                    float v11 = (sb + 1 <= tB) ? lif_s2(fmaf(gB, sacc[nt][3], bB)) : -1e30f;
                    sacc[nt][0] = v00; sacc[nt][1] = v01; sacc[nt][2] = v10; sacc[nt][3] = v11;
                    tmaxA = fmaxf(tmaxA, fmaxf(v00, v01));
                    tmaxB = fmaxf(tmaxB, fmaxf(v10, v11));
                }
            }
            tmaxA = fmaxf(tmaxA, __shfl_xor_sync(0xffffffffu, tmaxA, 1));
            tmaxA = fmaxf(tmaxA, __shfl_xor_sync(0xffffffffu, tmaxA, 2));
            tmaxB = fmaxf(tmaxB, __shfl_xor_sync(0xffffffffu, tmaxB, 1));
            tmaxB = fmaxf(tmaxB, __shfl_xor_sync(0xffffffffu, tmaxB, 2));

            if (__any_sync(0xffffffffu, (tmaxA > mA) || (tmaxB > mB))){
                float mAn = fmaxf(mA, tmaxA), mBn = fmaxf(mB, tmaxB);
                float scA = ex2_a(mA - mAn), scB = ex2_a(mB - mBn);
                mA = mAn; mB = mBn;
                #pragma unroll
                for (int nt = 0; nt < 8; nt++){
                    oacc[nt][0] *= scA; oacc[nt][1] *= scA;
                    oacc[nt][2] *= scB; oacc[nt][3] *= scB;
                }
                oaccS[0] *= scA; oaccS[1] *= scA;
                oaccS[2] *= scB; oaccS[3] *= scB;
            }

            // ---- packed fp16 exp -> P fragments
            uint32_t pa[4][4];
            #pragma unroll
            for (int nt = 0; nt < 8; nt++){
                __half2 hA = __floats2half2_rn(sacc[nt][0] - mA, sacc[nt][1] - mA);
                __half2 hB = __floats2half2_rn(sacc[nt][2] - mB, sacc[nt][3] - mB);
                uint32_t pA, pB;
                asm("ex2.approx.f16x2 %0, %1;" : "=r"(pA) : "r"(*(uint32_t*)&hA));
                asm("ex2.approx.f16x2 %0, %1;" : "=r"(pB) : "r"(*(uint32_t*)&hB));
                pa[nt >> 1][(nt & 1) * 2    ] = pA;
                pa[nt >> 1][(nt & 1) * 2 + 1] = pB;
            }

            // ---- MMA2: O += P.V  ; row sums via constant ones-fragment MMA
            #pragma unroll
            for (int kk = 0; kk < 4; kk++){
                uint32_t bfr[4][4];
                #pragma unroll
                for (int ng = 0; ng < 4; ng++){
                    uint32_t addr = (uint32_t)__cvta_generic_to_shared(
                        &Vb[(kk*16 + v_row) * HQ + ng*16 + v_col]);
                    asm volatile("ldmatrix.sync.aligned.m8n8.x4.trans.shared.b16 {%0,%1,%2,%3}, [%4];"
                        : "=r"(bfr[ng][0]), "=r"(bfr[ng][1]), "=r"(bfr[ng][2]), "=r"(bfr[ng][3])
                        : "r"(addr));
                }
                #pragma unroll
                for (int nt = 0; nt < 8; nt++){
                    uint32_t b0 = bfr[nt >> 1][(nt & 1) * 2];
                    uint32_t b1 = bfr[nt >> 1][(nt & 1) * 2 + 1];
                    asm volatile(
                        "mma.sync.aligned.m16n8k16.row.col.f32.f16.f16.f32 "
                        "{%0,%1,%2,%3},{%4,%5,%6,%7},{%8,%9},{%0,%1,%2,%3};"
                        : "+f"(oacc[nt][0]), "+f"(oacc[nt][1]),
                          "+f"(oacc[nt][2]), "+f"(oacc[nt][3])
                        : "r"(pa[kk][0]), "r"(pa[kk][1]), "r"(pa[kk][2]), "r"(pa[kk][3]),
                          "r"(b0), "r"(b1));
                }
                asm volatile(
                    "mma.sync.aligned.m16n8k16.row.col.f32.f16.f16.f32 "
                    "{%0,%1,%2,%3},{%4,%5,%6,%7},{%8,%9},{%0,%1,%2,%3};"
                    : "+f"(oaccS[0]), "+f"(oaccS[1]), "+f"(oaccS[2]), "+f"(oaccS[3])
                    : "r"(pa[kk][0]), "r"(pa[kk][1]), "r"(pa[kk][2]), "r"(pa[kk][3]),
                      "r"(ones_frag), "r"(ones_frag));
            }
        }
        buf ^= 1;
    }

    float psumA = __shfl_sync(0xffffffffu, oaccS[0], lane & 28);
    float psumB = __shfl_sync(0xffffffffu, oaccS[2], lane & 28);
    float invA = 1.0f / psumA;
    float invB = 1.0f / psumB;

    __half* opA = out + ((size_t)(b*Tt + tA)) * Cc + h*Dd;
    __half* opB = out + ((size_t)(b*Tt + tB)) * Cc + h*Dd;
    #pragma unroll
    for (int nt = 0; nt < 8; nt++){
        int d = nt*8 + cq;
        *(__half2*)&opA[d] = __floats2half2_rn(oacc[nt][0]*invA, oacc[nt][1]*invA);
        *(__half2*)&opB[d] = __floats2half2_rn(oacc[nt][2]*invB, oacc[nt][3]*invB);
    }
}

// ======================== launch ========================
extern "C" void kernel_launch(void* const* d_in, const int* in_sizes, int n_in,
                              void* d_out, int out_size){
    const float* x      = (const float*)d_in[0];
    const float* ln1_g  = (const float*)d_in[1];
    const float* ln1_b  = (const float*)d_in[2];
    const float* qkv_w  = (const float*)d_in[3];
    const float* qkv_b  = (const float*)d_in[4];
    const float* out_w  = (const float*)d_in[5];
    const float* out_b  = (const float*)d_in[6];
    const float* ln2_g  = (const float*)d_in[7];
    const float* ln2_b  = (const float*)d_in[8];
    const float* mlp_w1 = (const float*)d_in[9];
    const float* mlp_b1 = (const float*)d_in[10];
    const float* mlp_w2 = (const float*)d_in[11];
    const float* mlp_b2 = (const float*)d_in[12];
    const float* enc    = (const float*)d_in[13];
    const float* gain   = (const float*)d_in[14];
    const float* battn  = (const float*)d_in[15];
    float* outp = (float*)d_out;

    __half *xn, *qv, *att, *hbuf, *wqv, *wo, *w1, *w2, *eh;
    float *x1, *qvb;
    cudaGetSymbolAddress((void**)&xn,   g_xn);
    cudaGetSymbolAddress((void**)&qv,   g_qv);
    cudaGetSymbolAddress((void**)&att,  g_att);
    cudaGetSymbolAddress((void**)&x1,   g_x1);
    cudaGetSymbolAddress((void**)&hbuf, g_h);
    cudaGetSymbolAddress((void**)&wqv,  g_wqv);
    cudaGetSymbolAddress((void**)&wo,   g_wo);
    cudaGetSymbolAddress((void**)&w1,   g_w1);
    cudaGetSymbolAddress((void**)&w2,   g_w2);
    cudaGetSymbolAddress((void**)&qvb,  g_qvb);
    cudaGetSymbolAddress((void**)&eh,   g_eh);

    cudaFuncSetAttribute(attn_tc,       cudaFuncAttributeMaxDynamicSharedMemorySize, ATTN_SMEM);
    cudaFuncSetAttribute(gemm_h<true>,  cudaFuncAttributeMaxDynamicSharedMemorySize, GH_SMEM);
    cudaFuncSetAttribute(gemm_h<false>, cudaFuncAttributeMaxDynamicSharedMemorySize, GH_SMEM);

    const int M = Bb * Tt;

    prep_all<<<12296, dim3(32,8)>>>(qkv_w, out_w, mlp_w1, mlp_w2, qkv_b, enc,
                                    wqv, wo, w1, w2, qvb, eh);

    ln_kernel<<<M, 256>>>(x, ln1_g, ln1_b, xn);
    gemm_h<true ><<<dim3(2*Cc/128, M/128), 256, GH_SMEM>>>(xn, wqv, qvb, nullptr, qv, 2*Cc, Cc, 0);
    attn_tc<<<dim3(Tt/128, Bb*Hh), 256, ATTN_SMEM>>>(qv, qv + Cc, eh, gain, battn, att);
    gemm_h<false><<<dim3(Cc/128, M/128), 256, GH_SMEM>>>(att, wo, out_b, x, x1, Cc, Cc, 0);
    ln_kernel<<<M, 256>>>(x1, ln2_g, ln2_b, xn);
    gemm_h<true ><<<dim3(4*Cc/128, M/128), 256, GH_SMEM>>>(xn, w1, mlp_b1, nullptr, hbuf, 4*Cc, Cc, 1);
    gemm_h<false><<<dim3(Cc/128, M/128), 256, GH_SMEM>>>(hbuf, w2, mlp_b2, x1, outp, Cc, 4*Cc, 0);
}